// round 8
// baseline (speedup 1.0000x reference)
#include <cuda_runtime.h>
#include <cuda_bf16.h>
#include <math.h>
#include <stdint.h>

#define B_   2
#define S_   2048
#define H_   2048
#define NH_  16
#define D_   128
#define M_   (B_*S_)          // 4096 rows for all GEMMs

// ---------------- scratch (static device globals; no allocation) ------------
__device__ __align__(256) __nv_bfloat16 g_xh[(size_t)M_*H_];
__device__ __align__(256) __nv_bfloat16 g_xl[(size_t)M_*H_];
__device__ __align__(256) __nv_bfloat16 g_wh[(size_t)4*H_*H_];
__device__ __align__(256) __nv_bfloat16 g_wl[(size_t)4*H_*H_];
__device__ __align__(256) __nv_bfloat16 g_ah[(size_t)M_*H_];
__device__ __align__(256) __nv_bfloat16 g_al[(size_t)M_*H_];
__device__ __align__(256) __nv_bfloat16 g_qh[(size_t)B_*NH_*S_*D_];
__device__ __align__(256) __nv_bfloat16 g_ql[(size_t)B_*NH_*S_*D_];
__device__ __align__(256) __nv_bfloat16 g_kh[(size_t)B_*NH_*S_*D_];
__device__ __align__(256) __nv_bfloat16 g_kl[(size_t)B_*NH_*S_*D_];
__device__ __align__(256) __nv_bfloat16 g_vh[(size_t)B_*NH_*S_*D_];
__device__ __align__(256) __nv_bfloat16 g_vl[(size_t)B_*NH_*S_*D_];
__device__ __align__(256) float2 g_rope[(size_t)S_ * 64];   // (cos, sin)

// =========================== helpers ========================================
__device__ __forceinline__ uint32_t smem_u32(const void* p) {
    uint32_t a;
    asm("{ .reg .u64 t; cvta.to.shared.u64 t, %1; cvt.u32.u64 %0, t; }"
        : "=r"(a) : "l"(p));
    return a;
}
__device__ __forceinline__ void ldsm4(uint32_t& r0, uint32_t& r1,
                                      uint32_t& r2, uint32_t& r3, uint32_t a) {
    asm volatile("ldmatrix.sync.aligned.m8n8.x4.shared.b16 {%0,%1,%2,%3}, [%4];"
                 : "=r"(r0), "=r"(r1), "=r"(r2), "=r"(r3) : "r"(a));
}
__device__ __forceinline__ void ldsm4t(uint32_t& r0, uint32_t& r1,
                                       uint32_t& r2, uint32_t& r3, uint32_t a) {
    asm volatile("ldmatrix.sync.aligned.m8n8.x4.trans.shared.b16 {%0,%1,%2,%3}, [%4];"
                 : "=r"(r0), "=r"(r1), "=r"(r2), "=r"(r3) : "r"(a));
}
// NOTE: non-volatile on purpose — pure register op, lets ptxas schedule
// independent MMAs around each other.
__device__ __forceinline__ void mma16816(float* c, const uint32_t* a,
                                         const uint32_t* b) {
    asm("mma.sync.aligned.m16n8k16.row.col.f32.bf16.bf16.f32 "
        "{%0,%1,%2,%3}, {%4,%5,%6,%7}, {%8,%9}, {%0,%1,%2,%3};"
        : "+f"(c[0]), "+f"(c[1]), "+f"(c[2]), "+f"(c[3])
        : "r"(a[0]), "r"(a[1]), "r"(a[2]), "r"(a[3]), "r"(b[0]), "r"(b[1]));
}
__device__ __forceinline__ float ex2(float x) {
    float r;
    asm("ex2.approx.ftz.f32 %0, %1;" : "=f"(r) : "f"(x));
    return r;
}
__device__ __forceinline__ void split2(float a, float b, uint32_t& h, uint32_t& l) {
    __nv_bfloat16 ha = __float2bfloat16_rn(a), hb = __float2bfloat16_rn(b);
    __nv_bfloat16 la = __float2bfloat16_rn(a - __bfloat162float(ha));
    __nv_bfloat16 lb = __float2bfloat16_rn(b - __bfloat162float(hb));
    __nv_bfloat162 hv = __halves2bfloat162(ha, hb);
    __nv_bfloat162 lv = __halves2bfloat162(la, lb);
    h = *(uint32_t*)&hv; l = *(uint32_t*)&lv;
}
#define CP_ASYNC(sa, ga) \
    asm volatile("cp.async.cg.shared.global [%0], [%1], 16;" :: "r"(sa), "l"(ga))
#define CP_COMMIT() asm volatile("cp.async.commit_group;" ::: "memory")
#define CP_WAIT0()  asm volatile("cp.async.wait_group 0;" ::: "memory")
#define CP_WAIT1()  asm volatile("cp.async.wait_group 1;" ::: "memory")

// ====================== setup kernels =======================================
__global__ void __launch_bounds__(64)
rope_init_kernel()
{
    int s = blockIdx.x, p = threadIdx.x;
    float inv = expf(-(float)p * 0.14391156831212787f); // ln(10000)/64
    float ang = (float)s * inv;
    float sn, cs;
    sincosf(ang, &sn, &cs);
    g_rope[s * 64 + p] = make_float2(cs, sn);
}

__global__ void __launch_bounds__(256)
split_kernel(const float* __restrict__ src, __nv_bfloat16* __restrict__ hi,
             __nv_bfloat16* __restrict__ lo, int n)
{
    int i = (blockIdx.x * 256 + threadIdx.x) * 4;
    if (i >= n) return;
    float4 v = *(const float4*)(src + i);
    float vv[4] = {v.x, v.y, v.z, v.w};
    __nv_bfloat16 h[4], l[4];
#pragma unroll
    for (int q = 0; q < 4; q++) {
        h[q] = __float2bfloat16_rn(vv[q]);
        l[q] = __float2bfloat16_rn(vv[q] - __bfloat162float(h[q]));
    }
    *(uint2*)(hi + i) = *(uint2*)h;
    *(uint2*)(lo + i) = *(uint2*)l;
}

__global__ void __launch_bounds__(256)
split4_kernel(const float* __restrict__ s0, const float* __restrict__ s1,
              const float* __restrict__ s2, const float* __restrict__ s3,
              __nv_bfloat16* __restrict__ hi, __nv_bfloat16* __restrict__ lo, int n)
{
    const int z = blockIdx.y;
    const float* src = (z == 0) ? s0 : (z == 1) ? s1 : (z == 2) ? s2 : s3;
    int i = (blockIdx.x * 256 + threadIdx.x) * 4;
    if (i >= n) return;
    float4 v = *(const float4*)(src + i);
    float vv[4] = {v.x, v.y, v.z, v.w};
    __nv_bfloat16 h[4], l[4];
#pragma unroll
    for (int q = 0; q < 4; q++) {
        h[q] = __float2bfloat16_rn(vv[q]);
        l[q] = __float2bfloat16_rn(vv[q] - __bfloat162float(h[q]));
    }
    size_t o = (size_t)z * n + i;
    *(uint2*)(hi + o) = *(uint2*)h;
    *(uint2*)(lo + o) = *(uint2*)l;
}

// ============== bf16-split tensor-core GEMM (mma.sync path) =================
// C[M,N] = A[M,K] @ W[N,K]^T + bias, K=2048.
// Block tile 64(M) x 256(N), 8 warps 2x4, warp tile 32x64, BK=32,
// 2-stage cp.async pipeline, 2 CTAs/SM, interleaved MMA chains.
#define BKG     32
#define LDSTR   80
#define AL_OFF  (64 * LDSTR)             // 5120
#define BH_OFF  (2 * 64 * LDSTR)         // 10240
#define BL_OFF  (BH_OFF + 256 * LDSTR)   // 30720
#define STG     (BL_OFF + 256 * LDSTR)   // 51200
#define GSMEM   (2 * STG)                // 102400

__device__ __forceinline__ void g_load(uint32_t sbase,
    const __nv_bfloat16* A0, const __nv_bfloat16* A1,
    const __nv_bfloat16* B0, const __nv_bfloat16* B1, int k0, int tid)
{
    {
        int row = tid >> 2, c4 = tid & 3;
        CP_ASYNC(sbase + row * LDSTR + c4 * 16,
                 A0 + (size_t)row * H_ + k0 + c4 * 8);
        CP_ASYNC(sbase + AL_OFF + row * LDSTR + c4 * 16,
                 A1 + (size_t)row * H_ + k0 + c4 * 8);
    }
#pragma unroll
    for (int rep = 0; rep < 4; rep++) {
        int idx = tid + rep * 256;
        int row = idx >> 2, c4 = idx & 3;
        CP_ASYNC(sbase + BH_OFF + row * LDSTR + c4 * 16,
                 B0 + (size_t)row * H_ + k0 + c4 * 8);
        CP_ASYNC(sbase + BL_OFF + row * LDSTR + c4 * 16,
                 B1 + (size_t)row * H_ + k0 + c4 * 8);
    }
}

__global__ void __launch_bounds__(256, 2)
gemm_mma(const __nv_bfloat16* __restrict__ Ah, const __nv_bfloat16* __restrict__ Al,
         const __nv_bfloat16* __restrict__ WhB, const __nv_bfloat16* __restrict__ WlB,
         const float* __restrict__ b0, const float* __restrict__ b1,
         const float* __restrict__ b2,
         __nv_bfloat16* oh0, __nv_bfloat16* ol0,
         __nv_bfloat16* oh1, __nv_bfloat16* ol1,
         __nv_bfloat16* oh2, __nv_bfloat16* ol2,
         float* out, int fused)
{
    extern __shared__ char sm[];
    const uint32_t smb = smem_u32(sm);
    const int tid  = threadIdx.x;
    const int wid  = tid >> 5, lane = tid & 31;
    const int bm   = blockIdx.y * 64, bn = blockIdx.x * 256;
    const int wm   = (wid >> 2) * 32, wn = (wid & 3) * 64;

    const __nv_bfloat16* Wh = WhB;
    const __nv_bfloat16* Wl = WlB;
    const float* bias = b0;
    __nv_bfloat16 *oh = nullptr, *ol = nullptr;
    int mode = 2;
    if (fused) {
        const int z = blockIdx.z;
        Wh += (size_t)z * H_ * H_;
        Wl += (size_t)z * H_ * H_;
        bias = (z == 0) ? b0 : (z == 1) ? b1 : b2;
        oh   = (z == 0) ? oh0 : (z == 1) ? oh1 : oh2;
        ol   = (z == 0) ? ol0 : (z == 1) ? ol1 : ol2;
        mode = (z == 2) ? 0 : 1;
    }

    const __nv_bfloat16* A0 = Ah + (size_t)bm * H_;
    const __nv_bfloat16* A1 = Al + (size_t)bm * H_;
    const __nv_bfloat16* B0 = Wh + (size_t)bn * H_;
    const __nv_bfloat16* B1 = Wl + (size_t)bn * H_;

    float acc[2][8][4];
#pragma unroll
    for (int i = 0; i < 2; i++)
#pragma unroll
        for (int j = 0; j < 8; j++)
#pragma unroll
            for (int q = 0; q < 4; q++) acc[i][j][q] = 0.f;

    const int arow  = (lane & 7) + ((lane >> 3) & 1) * 8;
    const int acoff = ((lane >> 4) & 1) * 16;
    const int krow  = (lane & 7) + ((lane >> 4) & 1) * 8;
    const int kcoff = ((lane >> 3) & 1) * 16;

    g_load(smb, A0, A1, B0, B1, 0, tid);
    CP_COMMIT();

    const int NCH = H_ / BKG;   // 64
    for (int it = 0; it < NCH; it++) {
        if (it + 1 < NCH) {
            g_load(smb + ((it + 1) & 1) * STG, A0, A1, B0, B1,
                   (it + 1) * BKG, tid);
            CP_COMMIT();
            CP_WAIT1();
        } else {
            CP_WAIT0();
        }
        __syncthreads();

        const uint32_t st = smb + (uint32_t)(it & 1) * STG;
#pragma unroll
        for (int ks = 0; ks < 2; ks++) {
            const int kb = ks * 32;
            uint32_t ahf[2][4], alf[2][4];
#pragma unroll
            for (int mi = 0; mi < 2; mi++) {
                uint32_t off = (uint32_t)((wm + mi * 16 + arow) * LDSTR + kb + acoff);
                ldsm4(ahf[mi][0], ahf[mi][1], ahf[mi][2], ahf[mi][3], st + off);
                ldsm4(alf[mi][0], alf[mi][1], alf[mi][2], alf[mi][3], st + AL_OFF + off);
            }
#pragma unroll
            for (int nq = 0; nq < 4; nq++) {
                uint32_t off = (uint32_t)((wn + nq * 16 + krow) * LDSTR + kb + kcoff);
                uint32_t bh4[4], bl4[4];
                ldsm4(bh4[0], bh4[1], bh4[2], bh4[3], st + BH_OFF + off);
                ldsm4(bl4[0], bl4[1], bl4[2], bl4[3], st + BL_OFF + off);
                // interleaved: same-acc reuse distance = 4
                mma16816(acc[0][2*nq],   ahf[0], &bh4[0]);
                mma16816(acc[1][2*nq],   ahf[1], &bh4[0]);
                mma16816(acc[0][2*nq+1], ahf[0], &bh4[2]);
                mma16816(acc[1][2*nq+1], ahf[1], &bh4[2]);
                mma16816(acc[0][2*nq],   ahf[0], &bl4[0]);
                mma16816(acc[1][2*nq],   ahf[1], &bl4[0]);
                mma16816(acc[0][2*nq+1], ahf[0], &bl4[2]);
                mma16816(acc[1][2*nq+1], ahf[1], &bl4[2]);
                mma16816(acc[0][2*nq],   alf[0], &bh4[0]);
                mma16816(acc[1][2*nq],   alf[1], &bh4[0]);
                mma16816(acc[0][2*nq+1], alf[0], &bh4[2]);
                mma16816(acc[1][2*nq+1], alf[1], &bh4[2]);
            }
        }
        __syncthreads();
    }

    // ------------------------------ epilogue --------------------------------
    const int qrow = lane >> 2;
    const int qcol = (lane & 3) * 2;
#pragma unroll
    for (int mi = 0; mi < 2; mi++) {
#pragma unroll
        for (int half = 0; half < 2; half++) {
            const int m  = bm + wm + mi * 16 + qrow + half * 8;
            const int sI = m & (S_ - 1);
#pragma unroll
            for (int nj = 0; nj < 8; nj++) {
                const int n0 = bn + wn + nj * 8 + qcol;
                float v0 = acc[mi][nj][half * 2 + 0] + bias[n0];
                float v1 = acc[mi][nj][half * 2 + 1] + bias[n0 + 1];
                if (mode == 1) {
                    int pr = (n0 & (D_ - 1)) >> 1;
                    float2 cssn = g_rope[sI * 64 + pr];
                    float e = v0, o = v1;
                    v0 = e * cssn.x - o * cssn.y;
                    v1 = o * cssn.x + e * cssn.y;
                }
                if (mode == 2) {
                    *(float2*)(out + (size_t)m * H_ + n0) = make_float2(v0, v1);
                } else {
                    int b = m >> 11;
                    int h = n0 >> 7;
                    int dd = n0 & (D_ - 1);
                    size_t idx = (((size_t)(b * NH_ + h) * S_ + sI) << 7) + dd;
                    uint32_t hh, ll;
                    split2(v0, v1, hh, ll);
                    *(uint32_t*)(oh + idx) = hh;
                    *(uint32_t*)(ol + idx) = ll;
                }
            }
        }
    }
}

// ================= causal flash attention on tensor cores ===================
// 128 queries/block, 64-key tiles, 8 warps. Q hi+lo fragments in registers.
// K/V 3-stage cp.async pipeline, single barrier per tile, interleaved chains.
#define KSTR  272
#define ARRB  (64 * KSTR)             // 17408
#define STGB  (4 * ARRB)              // Kh,Kl,Vh,Vl per stage: 69632
#define ASMEM (3 * STGB)              // 208896

__device__ __forceinline__ void load_kv(uint32_t sb,
    const __nv_bfloat16* kh, const __nv_bfloat16* kl,
    const __nv_bfloat16* vh, const __nv_bfloat16* vl, size_t toff, int tid)
{
    const __nv_bfloat16* srcs[4] = {kh + toff, kl + toff, vh + toff, vl + toff};
#pragma unroll
    for (int arr = 0; arr < 4; arr++)
#pragma unroll
        for (int rep = 0; rep < 4; rep++) {
            int ch = tid + rep * 256;
            int row = ch >> 4, c = ch & 15;
            CP_ASYNC(sb + arr * ARRB + row * KSTR + c * 16,
                     srcs[arr] + row * D_ + c * 8);
        }
}

__global__ void __launch_bounds__(256, 1)
attn_mma(const __nv_bfloat16* __restrict__ Qh, const __nv_bfloat16* __restrict__ Ql,
         const __nv_bfloat16* __restrict__ Kh, const __nv_bfloat16* __restrict__ Kl,
         const __nv_bfloat16* __restrict__ Vh, const __nv_bfloat16* __restrict__ Vl,
         __nv_bfloat16* __restrict__ Oh, __nv_bfloat16* __restrict__ Ol)
{
    extern __shared__ char sm[];
    const uint32_t smb = smem_u32(sm);
    const int tid = threadIdx.x, wid = tid >> 5, lane = tid & 31;
    const int qt = blockIdx.x, h = blockIdx.y, b = blockIdx.z;
    const int bh = b * NH_ + h;
    const size_t qoff = ((size_t)bh * S_ + qt * 128) * D_;
    const __nv_bfloat16* kbh = Kh + (size_t)bh * S_ * D_;
    const __nv_bfloat16* kbl = Kl + (size_t)bh * S_ * D_;
    const __nv_bfloat16* vbh = Vh + (size_t)bh * S_ * D_;
    const __nv_bfloat16* vbl = Vl + (size_t)bh * S_ * D_;

#pragma unroll
    for (int rep = 0; rep < 8; rep++) {
        int ch = tid + rep * 256;
        int row = ch >> 4, c = ch & 15;
        CP_ASYNC(smb + row * KSTR + c * 16,        Qh + qoff + row * D_ + c * 8);
        CP_ASYNC(smb + STGB + row * KSTR + c * 16, Ql + qoff + row * D_ + c * 8);
    }
    CP_COMMIT(); CP_WAIT0();
    __syncthreads();

    const int arow  = (lane & 7) + ((lane >> 3) & 1) * 8;
    const int acoff = ((lane >> 4) & 1) * 16;
    uint32_t qh[8][4], ql[8][4];
#pragma unroll
    for (int kk = 0; kk < 8; kk++) {
        uint32_t off = (uint32_t)((wid * 16 + arow) * KSTR + kk * 32 + acoff);
        ldsm4(qh[kk][0], qh[kk][1], qh[kk][2], qh[kk][3], smb + off);
        ldsm4(ql[kk][0], ql[kk][1], ql[kk][2], ql[kk][3], smb + STGB + off);
    }
    __syncthreads();   // Q staging area free for K/V

    const int NT = 2 * qt + 2;

    load_kv(smb,        kbh, kbl, vbh, vbl, 0,               tid); CP_COMMIT();
    load_kv(smb + STGB, kbh, kbl, vbh, vbl, (size_t)64 * D_, tid); CP_COMMIT();

    float o[16][4];
#pragma unroll
    for (int nt = 0; nt < 16; nt++)
#pragma unroll
        for (int c = 0; c < 4; c++) o[nt][c] = 0.f;
    float mrow[2] = {-1e30f, -1e30f}, lrow[2] = {0.f, 0.f};
    const float CSc = 0.12752551286084458f;   // log2(e)/sqrt(128)

    const int krow  = (lane & 7) + ((lane >> 4) & 1) * 8;
    const int kcoff = ((lane >> 3) & 1) * 16;

    for (int it = 0; it < NT; it++) {
        if (it == NT - 1) { CP_WAIT0(); } else { CP_WAIT1(); }
        __syncthreads();
        const uint32_t st = smb + (uint32_t)(it % 3) * STGB;

        float s[8][4];
#pragma unroll
        for (int nj = 0; nj < 8; nj++)
#pragma unroll
            for (int c = 0; c < 4; c++) s[nj][c] = 0.f;

#pragma unroll
        for (int kk = 0; kk < 8; kk++) {
#pragma unroll
            for (int g = 0; g < 4; g++) {
                uint32_t off = (uint32_t)((g * 16 + krow) * KSTR + kk * 32 + kcoff);
                uint32_t kh4[4], kl4[4];
                ldsm4(kh4[0], kh4[1], kh4[2], kh4[3], st + off);
                ldsm4(kl4[0], kl4[1], kl4[2], kl4[3], st + ARRB + off);
                // interleaved: same-acc reuse distance = 2
                mma16816(s[2*g],   qh[kk], &kh4[0]);
                mma16816(s[2*g+1], qh[kk], &kh4[2]);
                mma16816(s[2*g],   qh[kk], &kl4[0]);
                mma16816(s[2*g+1], qh[kk], &kl4[2]);
                mma16816(s[2*g],   ql[kk], &kh4[0]);
                mma16816(s[2*g+1], ql[kk], &kh4[2]);
            }
        }

        if (it >= 2 * qt) {
            const int q0r = qt * 128 + wid * 16 + (lane >> 2);
            const int kc  = it * 64 + (lane & 3) * 2;
#pragma unroll
            for (int nj = 0; nj < 8; nj++) {
                int kcol = kc + nj * 8;
                if (kcol     > q0r)     s[nj][0] = -1e30f;
                if (kcol + 1 > q0r)     s[nj][1] = -1e30f;
                if (kcol     > q0r + 8) s[nj][2] = -1e30f;
                if (kcol + 1 > q0r + 8) s[nj][3] = -1e30f;
            }
        }

        float tm0 = -1e30f, tm1 = -1e30f;
#pragma unroll
        for (int nj = 0; nj < 8; nj++) {
            tm0 = fmaxf(tm0, fmaxf(s[nj][0], s[nj][1]));
            tm1 = fmaxf(tm1, fmaxf(s[nj][2], s[nj][3]));
        }
        tm0 = fmaxf(tm0, __shfl_xor_sync(0xffffffffu, tm0, 1));
        tm0 = fmaxf(tm0, __shfl_xor_sync(0xffffffffu, tm0, 2));
        tm1 = fmaxf(tm1, __shfl_xor_sync(0xffffffffu, tm1, 1));
        tm1 = fmaxf(tm1, __shfl_xor_sync(0xffffffffu, tm1, 2));
        float mn0 = fmaxf(mrow[0], tm0), mn1 = fmaxf(mrow[1], tm1);
        float cor0 = ex2(CSc * (mrow[0] - mn0));
        float cor1 = ex2(CSc * (mrow[1] - mn1));
        mrow[0] = mn0; mrow[1] = mn1;
        float rs0 = 0.f, rs1 = 0.f;
#pragma unroll
        for (int nj = 0; nj < 8; nj++) {
            s[nj][0] = ex2(CSc * (s[nj][0] - mn0)); rs0 += s[nj][0];
            s[nj][1] = ex2(CSc * (s[nj][1] - mn0)); rs0 += s[nj][1];
            s[nj][2] = ex2(CSc * (s[nj][2] - mn1)); rs1 += s[nj][2];
            s[nj][3] = ex2(CSc * (s[nj][3] - mn1)); rs1 += s[nj][3];
        }
        rs0 += __shfl_xor_sync(0xffffffffu, rs0, 1);
        rs0 += __shfl_xor_sync(0xffffffffu, rs0, 2);
        rs1 += __shfl_xor_sync(0xffffffffu, rs1, 1);
        rs1 += __shfl_xor_sync(0xffffffffu, rs1, 2);
        lrow[0] = lrow[0] * cor0 + rs0;
        lrow[1] = lrow[1] * cor1 + rs1;
#pragma unroll
        for (int nt = 0; nt < 16; nt++) {
            o[nt][0] *= cor0; o[nt][1] *= cor0;
            o[nt][2] *= cor1; o[nt][3] *= cor1;
        }

        uint32_t ph[4][4], pl[4][4];
#pragma unroll
        for (int t = 0; t < 4; t++) {
            split2(s[2*t][0],   s[2*t][1],   ph[t][0], pl[t][0]);
            split2(s[2*t][2],   s[2*t][3],   ph[t][1], pl[t][1]);
            split2(s[2*t+1][0], s[2*t+1][1], ph[t][2], pl[t][2]);
            split2(s[2*t+1][2], s[2*t+1][3], ph[t][3], pl[t][3]);
        }

#pragma unroll
        for (int t = 0; t < 4; t++) {
#pragma unroll
            for (int nc = 0; nc < 8; nc++) {
                uint32_t off = (uint32_t)((t * 16 + arow) * KSTR + nc * 32 + acoff);
                uint32_t vh4[4], vl4[4];
                ldsm4t(vh4[0], vh4[1], vh4[2], vh4[3], st + 2 * ARRB + off);
                ldsm4t(vl4[0], vl4[1], vl4[2], vl4[3], st + 3 * ARRB + off);
                // interleaved: same-acc reuse distance = 2
                mma16816(o[2*nc],   ph[t], &vh4[0]);
                mma16816(o[2*nc+1], ph[t], &vh4[2]);
                mma16816(o[2*nc],   ph[t], &vl4[0]);
                mma16816(o[2*nc+1], ph[t], &vl4[2]);
                mma16816(o[2*nc],   pl[t], &vh4[0]);
                mma16816(o[2*nc+1], pl[t], &vh4[2]);
            }
        }

        if (it + 2 < NT) {
            load_kv(smb + (uint32_t)((it + 2) % 3) * STGB,
                    kbh, kbl, vbh, vbl, (size_t)(it + 2) * 64 * D_, tid);
            CP_COMMIT();
        }
    }

    const float inv0 = 1.f / lrow[0], inv1 = 1.f / lrow[1];
    const int q0 = qt * 128 + wid * 16 + (lane >> 2);
    const size_t base0 = ((size_t)(b * S_) + q0) * H_ + h * 128;
    const size_t base1 = base0 + (size_t)8 * H_;
#pragma unroll
    for (int nt = 0; nt < 16; nt++) {
        const int col = nt * 8 + (lane & 3) * 2;
        uint32_t hh, ll;
        split2(o[nt][0] * inv0, o[nt][1] * inv0, hh, ll);
        *(uint32_t*)(Oh + base0 + col) = hh;
        *(uint32_t*)(Ol + base0 + col) = ll;
        split2(o[nt][2] * inv1, o[nt][3] * inv1, hh, ll);
        *(uint32_t*)(Oh + base1 + col) = hh;
        *(uint32_t*)(Ol + base1 + col) = ll;
    }
}

// ============================================================================
extern "C" void kernel_launch(void* const* d_in, const int* in_sizes, int n_in,
                              void* d_out, int out_size)
{
    const float* x  = (const float*)d_in[0];
    const float* Wq = (const float*)d_in[1];
    const float* bq = (const float*)d_in[2];
    const float* Wk = (const float*)d_in[3];
    const float* bk = (const float*)d_in[4];
    const float* Wv = (const float*)d_in[5];
    const float* bv = (const float*)d_in[6];
    const float* Wo = (const float*)d_in[7];
    const float* bo = (const float*)d_in[8];
    float* out = (float*)d_out;

    __nv_bfloat16 *xh, *xl, *wh, *wl, *ah, *al;
    __nv_bfloat16 *qh, *ql, *kh, *kl, *vh, *vl;
    cudaGetSymbolAddress((void**)&xh, g_xh);
    cudaGetSymbolAddress((void**)&xl, g_xl);
    cudaGetSymbolAddress((void**)&wh, g_wh);
    cudaGetSymbolAddress((void**)&wl, g_wl);
    cudaGetSymbolAddress((void**)&ah, g_ah);
    cudaGetSymbolAddress((void**)&al, g_al);
    cudaGetSymbolAddress((void**)&qh, g_qh);
    cudaGetSymbolAddress((void**)&ql, g_ql);
    cudaGetSymbolAddress((void**)&kh, g_kh);
    cudaGetSymbolAddress((void**)&kl, g_kl);
    cudaGetSymbolAddress((void**)&vh, g_vh);
    cudaGetSymbolAddress((void**)&vl, g_vl);

    cudaFuncSetAttribute(gemm_mma,
                         cudaFuncAttributeMaxDynamicSharedMemorySize, GSMEM);
    cudaFuncSetAttribute(attn_mma,
                         cudaFuncAttributeMaxDynamicSharedMemorySize, ASMEM);

    const int nX = M_ * H_;
    const int nW = H_ * H_;
    rope_init_kernel<<<S_, 64>>>();
    split_kernel<<<nX / 1024, 256>>>(x, xh, xl, nX);
    split4_kernel<<<dim3(nW / 1024, 4), 256>>>(Wq, Wk, Wv, Wo, wh, wl, nW);

    dim3 gq(H_ / 256, M_ / 64, 3);
    gemm_mma<<<gq, 256, GSMEM>>>(xh, xl, wh, wl, bq, bk, bv,
                                 qh, ql, kh, kl, vh, vl, nullptr, 1);

    attn_mma<<<dim3(S_ / 128, NH_, B_), 256, ASMEM>>>(qh, ql, kh, kl, vh, vl, ah, al);

    dim3 go(H_ / 256, M_ / 64, 1);
    gemm_mma<<<go, 256, GSMEM>>>(ah, al, wh + 3*(size_t)nW, wl + 3*(size_t)nW,
                                 bo, nullptr, nullptr,
                                 nullptr, nullptr, nullptr, nullptr, nullptr, nullptr,
                                 out, 0);
}

// round 9
// speedup vs baseline: 1.5238x; 1.5238x over previous
#include <cuda_runtime.h>
#include <cuda_fp16.h>
#include <math.h>
#include <stdint.h>

#define B_   2
#define S_   2048
#define H_   2048
#define NH_  16
#define D_   128
#define M_   (B_*S_)          // 4096 rows for all GEMMs

// ---------------- scratch (static device globals; no allocation) ------------
__device__ __align__(256) __half g_xh[(size_t)M_*H_];
__device__ __align__(256) __half g_xl[(size_t)M_*H_];
__device__ __align__(256) __half g_wh[(size_t)4*H_*H_];     // weights, hi only
__device__ __align__(256) __half g_ah[(size_t)M_*H_];       // attn out hi
__device__ __align__(256) __half g_al[(size_t)M_*H_];       // attn out lo
__device__ __align__(256) __half g_qh[(size_t)B_*NH_*S_*D_];
__device__ __align__(256) __half g_ql[(size_t)B_*NH_*S_*D_];
__device__ __align__(256) __half g_kh[(size_t)B_*NH_*S_*D_]; // K hi only
__device__ __align__(256) __half g_vh[(size_t)B_*NH_*S_*D_]; // V hi only
__device__ __align__(256) float2 g_rope[(size_t)S_ * 64];    // (cos, sin)

// =========================== helpers ========================================
__device__ __forceinline__ uint32_t smem_u32(const void* p) {
    uint32_t a;
    asm("{ .reg .u64 t; cvta.to.shared.u64 t, %1; cvt.u32.u64 %0, t; }"
        : "=r"(a) : "l"(p));
    return a;
}
__device__ __forceinline__ void ldsm4(uint32_t& r0, uint32_t& r1,
                                      uint32_t& r2, uint32_t& r3, uint32_t a) {
    asm volatile("ldmatrix.sync.aligned.m8n8.x4.shared.b16 {%0,%1,%2,%3}, [%4];"
                 : "=r"(r0), "=r"(r1), "=r"(r2), "=r"(r3) : "r"(a));
}
__device__ __forceinline__ void ldsm4t(uint32_t& r0, uint32_t& r1,
                                       uint32_t& r2, uint32_t& r3, uint32_t a) {
    asm volatile("ldmatrix.sync.aligned.m8n8.x4.trans.shared.b16 {%0,%1,%2,%3}, [%4];"
                 : "=r"(r0), "=r"(r1), "=r"(r2), "=r"(r3) : "r"(a));
}
// fp16 MMA, fp32 accumulate; non-volatile so ptxas may schedule freely.
__device__ __forceinline__ void mma16816(float* c, const uint32_t* a,
                                         const uint32_t* b) {
    asm("mma.sync.aligned.m16n8k16.row.col.f32.f16.f16.f32 "
        "{%0,%1,%2,%3}, {%4,%5,%6,%7}, {%8,%9}, {%0,%1,%2,%3};"
        : "+f"(c[0]), "+f"(c[1]), "+f"(c[2]), "+f"(c[3])
        : "r"(a[0]), "r"(a[1]), "r"(a[2]), "r"(a[3]), "r"(b[0]), "r"(b[1]));
}
__device__ __forceinline__ float ex2(float x) {
    float r;
    asm("ex2.approx.ftz.f32 %0, %1;" : "=f"(r) : "f"(x));
    return r;
}
// fp32 pair -> fp16 hi + fp16 lo (packed half2 words)
__device__ __forceinline__ void split2h(float a, float b, uint32_t& h, uint32_t& l) {
    __half ha = __float2half_rn(a), hb = __float2half_rn(b);
    __half la = __float2half_rn(a - __half2float(ha));
    __half lb = __float2half_rn(b - __half2float(hb));
    __half2 hv = __halves2half2(ha, hb);
    __half2 lv = __halves2half2(la, lb);
    h = *(uint32_t*)&hv; l = *(uint32_t*)&lv;
}
__device__ __forceinline__ uint32_t pack2h(float a, float b) {
    __half2 hv = __halves2half2(__float2half_rn(a), __float2half_rn(b));
    return *(uint32_t*)&hv;
}
#define CP_ASYNC(sa, ga) \
    asm volatile("cp.async.cg.shared.global [%0], [%1], 16;" :: "r"(sa), "l"(ga))
#define CP_COMMIT() asm volatile("cp.async.commit_group;" ::: "memory")
#define CP_WAIT0()  asm volatile("cp.async.wait_group 0;" ::: "memory")
#define CP_WAIT1()  asm volatile("cp.async.wait_group 1;" ::: "memory")

// ====================== setup kernels =======================================
__global__ void __launch_bounds__(64)
rope_init_kernel()
{
    int s = blockIdx.x, p = threadIdx.x;
    float inv = expf(-(float)p * 0.14391156831212787f); // ln(10000)/64
    float ang = (float)s * inv;
    float sn, cs;
    sincosf(ang, &sn, &cs);
    g_rope[s * 64 + p] = make_float2(cs, sn);
}

// x -> fp16 hi/lo pair
__global__ void __launch_bounds__(256)
split_kernel(const float* __restrict__ src, __half* __restrict__ hi,
             __half* __restrict__ lo, int n)
{
    int i = (blockIdx.x * 256 + threadIdx.x) * 4;
    if (i >= n) return;
    float4 v = *(const float4*)(src + i);
    float vv[4] = {v.x, v.y, v.z, v.w};
    __half h[4], l[4];
#pragma unroll
    for (int q = 0; q < 4; q++) {
        h[q] = __float2half_rn(vv[q]);
        l[q] = __float2half_rn(vv[q] - __half2float(h[q]));
    }
    *(uint2*)(hi + i) = *(uint2*)h;
    *(uint2*)(lo + i) = *(uint2*)l;
}

// four weight matrices -> single fp16 (hi only), z selects source
__global__ void __launch_bounds__(256)
round4_kernel(const float* __restrict__ s0, const float* __restrict__ s1,
              const float* __restrict__ s2, const float* __restrict__ s3,
              __half* __restrict__ dst, int n)
{
    const int z = blockIdx.y;
    const float* src = (z == 0) ? s0 : (z == 1) ? s1 : (z == 2) ? s2 : s3;
    int i = (blockIdx.x * 256 + threadIdx.x) * 4;
    if (i >= n) return;
    float4 v = *(const float4*)(src + i);
    __half h[4] = {__float2half_rn(v.x), __float2half_rn(v.y),
                   __float2half_rn(v.z), __float2half_rn(v.w)};
    *(uint2*)(dst + (size_t)z * n + i) = *(uint2*)h;
}

// ============== fp16 2-term tensor-core GEMM (mma.sync path) ================
// C[M,N] = (Ah+Al)[M,K] @ W[N,K]^T + bias, K=2048, W single fp16.
// Block tile 64(M) x 256(N), 8 warps 2x4, warp tile 32x64, BK=32,
// 2-stage cp.async pipeline, 2 CTAs/SM.
// mode 0: [b,h,s,d] hi only (V) | 1: RoPE, hi+lo (Q) | 2: fp32 [M,N] (out)
// mode 3: RoPE, hi only (K)
#define BKG     32
#define LDSTR   80
#define AL_OFF  (64 * LDSTR)             // 5120
#define B_OFF   (2 * 64 * LDSTR)         // 10240
#define STG     (B_OFF + 256 * LDSTR)    // 30720
#define GSMEM   (2 * STG)                // 61440

__device__ __forceinline__ void g_load(uint32_t sbase,
    const __half* A0, const __half* A1, const __half* B0, int k0, int tid)
{
    {
        int row = tid >> 2, c4 = tid & 3;
        CP_ASYNC(sbase + row * LDSTR + c4 * 16,
                 A0 + (size_t)row * H_ + k0 + c4 * 8);
        CP_ASYNC(sbase + AL_OFF + row * LDSTR + c4 * 16,
                 A1 + (size_t)row * H_ + k0 + c4 * 8);
    }
#pragma unroll
    for (int rep = 0; rep < 4; rep++) {
        int idx = tid + rep * 256;
        int row = idx >> 2, c4 = idx & 3;
        CP_ASYNC(sbase + B_OFF + row * LDSTR + c4 * 16,
                 B0 + (size_t)row * H_ + k0 + c4 * 8);
    }
}

__global__ void __launch_bounds__(256, 2)
gemm_mma(const __half* __restrict__ Ah, const __half* __restrict__ Al,
         const __half* __restrict__ WB,
         const float* __restrict__ b0, const float* __restrict__ b1,
         const float* __restrict__ b2,
         __half* o0h, __half* o0l, __half* o1h, __half* o2h,
         float* out, int fused)
{
    extern __shared__ char sm[];
    const uint32_t smb = smem_u32(sm);
    const int tid  = threadIdx.x;
    const int wid  = tid >> 5, lane = tid & 31;
    const int bm   = blockIdx.y * 64, bn = blockIdx.x * 256;
    const int wm   = (wid >> 2) * 32, wn = (wid & 3) * 64;

    const __half* W = WB;
    const float* bias = b0;
    __half *oh = nullptr, *ol = nullptr;
    int mode = 2;
    if (fused) {
        const int z = blockIdx.z;
        W += (size_t)z * H_ * H_;
        bias = (z == 0) ? b0 : (z == 1) ? b1 : b2;
        oh   = (z == 0) ? o0h : (z == 1) ? o1h : o2h;
        ol   = (z == 0) ? o0l : nullptr;
        mode = (z == 0) ? 1 : (z == 1) ? 3 : 0;
    }

    const __half* A0 = Ah + (size_t)bm * H_;
    const __half* A1 = Al + (size_t)bm * H_;
    const __half* B0 = W  + (size_t)bn * H_;

    float acc[2][8][4];
#pragma unroll
    for (int i = 0; i < 2; i++)
#pragma unroll
        for (int j = 0; j < 8; j++)
#pragma unroll
            for (int q = 0; q < 4; q++) acc[i][j][q] = 0.f;

    const int arow  = (lane & 7) + ((lane >> 3) & 1) * 8;
    const int acoff = ((lane >> 4) & 1) * 16;
    const int krow  = (lane & 7) + ((lane >> 4) & 1) * 8;
    const int kcoff = ((lane >> 3) & 1) * 16;

    g_load(smb, A0, A1, B0, 0, tid);
    CP_COMMIT();

    const int NCH = H_ / BKG;   // 64
    for (int it = 0; it < NCH; it++) {
        if (it + 1 < NCH) {
            g_load(smb + ((it + 1) & 1) * STG, A0, A1, B0, (it + 1) * BKG, tid);
            CP_COMMIT();
            CP_WAIT1();
        } else {
            CP_WAIT0();
        }
        __syncthreads();

        const uint32_t st = smb + (uint32_t)(it & 1) * STG;
#pragma unroll
        for (int ks = 0; ks < 2; ks++) {
            const int kb = ks * 32;
            uint32_t ahf[2][4], alf[2][4];
#pragma unroll
            for (int mi = 0; mi < 2; mi++) {
                uint32_t off = (uint32_t)((wm + mi * 16 + arow) * LDSTR + kb + acoff);
                ldsm4(ahf[mi][0], ahf[mi][1], ahf[mi][2], ahf[mi][3], st + off);
                ldsm4(alf[mi][0], alf[mi][1], alf[mi][2], alf[mi][3], st + AL_OFF + off);
            }
#pragma unroll
            for (int nq = 0; nq < 4; nq++) {
                uint32_t off = (uint32_t)((wn + nq * 16 + krow) * LDSTR + kb + kcoff);
                uint32_t b4[4];
                ldsm4(b4[0], b4[1], b4[2], b4[3], st + B_OFF + off);
                mma16816(acc[0][2*nq],   ahf[0], &b4[0]);
                mma16816(acc[1][2*nq],   ahf[1], &b4[0]);
                mma16816(acc[0][2*nq+1], ahf[0], &b4[2]);
                mma16816(acc[1][2*nq+1], ahf[1], &b4[2]);
                mma16816(acc[0][2*nq],   alf[0], &b4[0]);
                mma16816(acc[1][2*nq],   alf[1], &b4[0]);
                mma16816(acc[0][2*nq+1], alf[0], &b4[2]);
                mma16816(acc[1][2*nq+1], alf[1], &b4[2]);
            }
        }
        __syncthreads();
    }

    // ------------------------------ epilogue --------------------------------
    const int qrow = lane >> 2;
    const int qcol = (lane & 3) * 2;
#pragma unroll
    for (int mi = 0; mi < 2; mi++) {
#pragma unroll
        for (int half_ = 0; half_ < 2; half_++) {
            const int m  = bm + wm + mi * 16 + qrow + half_ * 8;
            const int sI = m & (S_ - 1);
#pragma unroll
            for (int nj = 0; nj < 8; nj++) {
                const int n0 = bn + wn + nj * 8 + qcol;
                float v0 = acc[mi][nj][half_ * 2 + 0] + bias[n0];
                float v1 = acc[mi][nj][half_ * 2 + 1] + bias[n0 + 1];
                if (mode == 1 || mode == 3) {
                    int pr = (n0 & (D_ - 1)) >> 1;
                    float2 cssn = g_rope[sI * 64 + pr];
                    float e = v0, o = v1;
                    v0 = e * cssn.x - o * cssn.y;
                    v1 = o * cssn.x + e * cssn.y;
                }
                if (mode == 2) {
                    *(float2*)(out + (size_t)m * H_ + n0) = make_float2(v0, v1);
                } else {
                    int b = m >> 11;
                    int h = n0 >> 7;
                    int dd = n0 & (D_ - 1);
                    size_t idx = (((size_t)(b * NH_ + h) * S_ + sI) << 7) + dd;
                    if (mode == 1) {
                        uint32_t hh, ll;
                        split2h(v0, v1, hh, ll);
                        *(uint32_t*)(oh + idx) = hh;
                        *(uint32_t*)(ol + idx) = ll;
                    } else {
                        *(uint32_t*)(oh + idx) = pack2h(v0, v1);
                    }
                }
            }
        }
    }
}

// ================= causal flash attention on tensor cores ===================
// 128 queries/block, 64-key tiles, 8 warps. Q hi+lo fragments in registers.
// K, V single fp16 in smem; P split fp16 in registers (2-term PV).
// 3-stage cp.async pipeline, single barrier per tile.
#define KSTR  272
#define ARRB  (64 * KSTR)             // 17408
#define STGB  (2 * ARRB)              // K, V per stage: 34816
#define ASMEM (3 * STGB)              // 104448

__device__ __forceinline__ void load_kv(uint32_t sb,
    const __half* kh, const __half* vh, size_t toff, int tid)
{
    const __half* srcs[2] = {kh + toff, vh + toff};
#pragma unroll
    for (int arr = 0; arr < 2; arr++)
#pragma unroll
        for (int rep = 0; rep < 4; rep++) {
            int ch = tid + rep * 256;
            int row = ch >> 4, c = ch & 15;
            CP_ASYNC(sb + arr * ARRB + row * KSTR + c * 16,
                     srcs[arr] + row * D_ + c * 8);
        }
}

__global__ void __launch_bounds__(256, 1)
attn_mma(const __half* __restrict__ Qh, const __half* __restrict__ Ql,
         const __half* __restrict__ Kh, const __half* __restrict__ Vh,
         __half* __restrict__ Oh, __half* __restrict__ Ol)
{
    extern __shared__ char sm[];
    const uint32_t smb = smem_u32(sm);
    const int tid = threadIdx.x, wid = tid >> 5, lane = tid & 31;
    const int qt = blockIdx.x, h = blockIdx.y, b = blockIdx.z;
    const int bh = b * NH_ + h;
    const size_t qoff = ((size_t)bh * S_ + qt * 128) * D_;
    const __half* kbh = Kh + (size_t)bh * S_ * D_;
    const __half* vbh = Vh + (size_t)bh * S_ * D_;

    // ---- stage Q: Qh -> slot0, Ql -> slot1; extract frags to registers -----
#pragma unroll
    for (int rep = 0; rep < 8; rep++) {
        int ch = tid + rep * 256;
        int row = ch >> 4, c = ch & 15;
        CP_ASYNC(smb + row * KSTR + c * 16,        Qh + qoff + row * D_ + c * 8);
        CP_ASYNC(smb + STGB + row * KSTR + c * 16, Ql + qoff + row * D_ + c * 8);
    }
    CP_COMMIT(); CP_WAIT0();
    __syncthreads();

    const int arow  = (lane & 7) + ((lane >> 3) & 1) * 8;
    const int acoff = ((lane >> 4) & 1) * 16;
    uint32_t qh[8][4], ql[8][4];
#pragma unroll
    for (int kk = 0; kk < 8; kk++) {
        uint32_t off = (uint32_t)((wid * 16 + arow) * KSTR + kk * 32 + acoff);
        ldsm4(qh[kk][0], qh[kk][1], qh[kk][2], qh[kk][3], smb + off);
        ldsm4(ql[kk][0], ql[kk][1], ql[kk][2], ql[kk][3], smb + STGB + off);
    }
    __syncthreads();   // Q staging area free for K/V

    const int NT = 2 * qt + 2;

    load_kv(smb,        kbh, vbh, 0,               tid); CP_COMMIT();
    load_kv(smb + STGB, kbh, vbh, (size_t)64 * D_, tid); CP_COMMIT();

    float o[16][4];
#pragma unroll
    for (int nt = 0; nt < 16; nt++)
#pragma unroll
        for (int c = 0; c < 4; c++) o[nt][c] = 0.f;
    float mrow[2] = {-1e30f, -1e30f}, lrow[2] = {0.f, 0.f};
    const float CSc = 0.12752551286084458f;   // log2(e)/sqrt(128)

    const int krow  = (lane & 7) + ((lane >> 4) & 1) * 8;
    const int kcoff = ((lane >> 3) & 1) * 16;

    for (int it = 0; it < NT; it++) {
        if (it == NT - 1) { CP_WAIT0(); } else { CP_WAIT1(); }
        __syncthreads();
        const uint32_t st = smb + (uint32_t)(it % 3) * STGB;

        // ---------------- S = Q @ K^T (2-term: qh, ql vs single K) ----------
        float s[8][4];
#pragma unroll
        for (int nj = 0; nj < 8; nj++)
#pragma unroll
            for (int c = 0; c < 4; c++) s[nj][c] = 0.f;

#pragma unroll
        for (int kk = 0; kk < 8; kk++) {
#pragma unroll
            for (int g = 0; g < 4; g++) {
                uint32_t off = (uint32_t)((g * 16 + krow) * KSTR + kk * 32 + kcoff);
                uint32_t k4[4];
                ldsm4(k4[0], k4[1], k4[2], k4[3], st + off);
                mma16816(s[2*g],   qh[kk], &k4[0]);
                mma16816(s[2*g+1], qh[kk], &k4[2]);
                mma16816(s[2*g],   ql[kk], &k4[0]);
                mma16816(s[2*g+1], ql[kk], &k4[2]);
            }
        }

        // ---------------- causal mask (last two tiles only) -----------------
        if (it >= 2 * qt) {
            const int q0r = qt * 128 + wid * 16 + (lane >> 2);
            const int kc  = it * 64 + (lane & 3) * 2;
#pragma unroll
            for (int nj = 0; nj < 8; nj++) {
                int kcol = kc + nj * 8;
                if (kcol     > q0r)     s[nj][0] = -1e30f;
                if (kcol + 1 > q0r)     s[nj][1] = -1e30f;
                if (kcol     > q0r + 8) s[nj][2] = -1e30f;
                if (kcol + 1 > q0r + 8) s[nj][3] = -1e30f;
            }
        }

        // ---------------- online softmax ------------------------------------
        float tm0 = -1e30f, tm1 = -1e30f;
#pragma unroll
        for (int nj = 0; nj < 8; nj++) {
            tm0 = fmaxf(tm0, fmaxf(s[nj][0], s[nj][1]));
            tm1 = fmaxf(tm1, fmaxf(s[nj][2], s[nj][3]));
        }
        tm0 = fmaxf(tm0, __shfl_xor_sync(0xffffffffu, tm0, 1));
        tm0 = fmaxf(tm0, __shfl_xor_sync(0xffffffffu, tm0, 2));
        tm1 = fmaxf(tm1, __shfl_xor_sync(0xffffffffu, tm1, 1));
        tm1 = fmaxf(tm1, __shfl_xor_sync(0xffffffffu, tm1, 2));
        float mn0 = fmaxf(mrow[0], tm0), mn1 = fmaxf(mrow[1], tm1);
        float cor0 = ex2(CSc * (mrow[0] - mn0));
        float cor1 = ex2(CSc * (mrow[1] - mn1));
        mrow[0] = mn0; mrow[1] = mn1;
        float rs0 = 0.f, rs1 = 0.f;
#pragma unroll
        for (int nj = 0; nj < 8; nj++) {
            s[nj][0] = ex2(CSc * (s[nj][0] - mn0)); rs0 += s[nj][0];
            s[nj][1] = ex2(CSc * (s[nj][1] - mn0)); rs0 += s[nj][1];
            s[nj][2] = ex2(CSc * (s[nj][2] - mn1)); rs1 += s[nj][2];
            s[nj][3] = ex2(CSc * (s[nj][3] - mn1)); rs1 += s[nj][3];
        }
        rs0 += __shfl_xor_sync(0xffffffffu, rs0, 1);
        rs0 += __shfl_xor_sync(0xffffffffu, rs0, 2);
        rs1 += __shfl_xor_sync(0xffffffffu, rs1, 1);
        rs1 += __shfl_xor_sync(0xffffffffu, rs1, 2);
        lrow[0] = lrow[0] * cor0 + rs0;
        lrow[1] = lrow[1] * cor1 + rs1;
#pragma unroll
        for (int nt = 0; nt < 16; nt++) {
            o[nt][0] *= cor0; o[nt][1] *= cor0;
            o[nt][2] *= cor1; o[nt][3] *= cor1;
        }

        // ---------------- P -> fp16 hi/lo a-frags (registers only) ----------
        uint32_t ph[4][4], pl[4][4];
#pragma unroll
        for (int t = 0; t < 4; t++) {
            split2h(s[2*t][0],   s[2*t][1],   ph[t][0], pl[t][0]);
            split2h(s[2*t][2],   s[2*t][3],   ph[t][1], pl[t][1]);
            split2h(s[2*t+1][0], s[2*t+1][1], ph[t][2], pl[t][2]);
            split2h(s[2*t+1][2], s[2*t+1][3], ph[t][3], pl[t][3]);
        }

        // ---------------- O += P @ V (2-term: ph, pl vs single V) -----------
#pragma unroll
        for (int t = 0; t < 4; t++) {
#pragma unroll
            for (int nc = 0; nc < 8; nc++) {
                uint32_t off = (uint32_t)((t * 16 + arow) * KSTR + nc * 32 + acoff);
                uint32_t v4[4];
                ldsm4t(v4[0], v4[1], v4[2], v4[3], st + ARRB + off);
                mma16816(o[2*nc],   ph[t], &v4[0]);
                mma16816(o[2*nc+1], ph[t], &v4[2]);
                mma16816(o[2*nc],   pl[t], &v4[0]);
                mma16816(o[2*nc+1], pl[t], &v4[2]);
            }
        }

        if (it + 2 < NT) {
            load_kv(smb + (uint32_t)((it + 2) % 3) * STGB,
                    kbh, vbh, (size_t)(it + 2) * 64 * D_, tid);
            CP_COMMIT();
        }
    }

    // ---------------- epilogue: O/l -> fp16 hi/lo, [b*s, h*d] ---------------
    const float inv0 = 1.f / lrow[0], inv1 = 1.f / lrow[1];
    const int q0 = qt * 128 + wid * 16 + (lane >> 2);
    const size_t base0 = ((size_t)(b * S_) + q0) * H_ + h * 128;
    const size_t base1 = base0 + (size_t)8 * H_;
#pragma unroll
    for (int nt = 0; nt < 16; nt++) {
        const int col = nt * 8 + (lane & 3) * 2;
        uint32_t hh, ll;
        split2h(o[nt][0] * inv0, o[nt][1] * inv0, hh, ll);
        *(uint32_t*)(Oh + base0 + col) = hh;
        *(uint32_t*)(Ol + base0 + col) = ll;
        split2h(o[nt][2] * inv1, o[nt][3] * inv1, hh, ll);
        *(uint32_t*)(Oh + base1 + col) = hh;
        *(uint32_t*)(Ol + base1 + col) = ll;
    }
}

// ============================================================================
extern "C" void kernel_launch(void* const* d_in, const int* in_sizes, int n_in,
                              void* d_out, int out_size)
{
    const float* x  = (const float*)d_in[0];
    const float* Wq = (const float*)d_in[1];
    const float* bq = (const float*)d_in[2];
    const float* Wk = (const float*)d_in[3];
    const float* bk = (const float*)d_in[4];
    const float* Wv = (const float*)d_in[5];
    const float* bv = (const float*)d_in[6];
    const float* Wo = (const float*)d_in[7];
    const float* bo = (const float*)d_in[8];
    float* out = (float*)d_out;

    __half *xh, *xl, *wh, *ah, *al, *qh, *ql, *kh, *vh;
    cudaGetSymbolAddress((void**)&xh, g_xh);
    cudaGetSymbolAddress((void**)&xl, g_xl);
    cudaGetSymbolAddress((void**)&wh, g_wh);
    cudaGetSymbolAddress((void**)&ah, g_ah);
    cudaGetSymbolAddress((void**)&al, g_al);
    cudaGetSymbolAddress((void**)&qh, g_qh);
    cudaGetSymbolAddress((void**)&ql, g_ql);
    cudaGetSymbolAddress((void**)&kh, g_kh);
    cudaGetSymbolAddress((void**)&vh, g_vh);

    cudaFuncSetAttribute(gemm_mma,
                         cudaFuncAttributeMaxDynamicSharedMemorySize, GSMEM);
    cudaFuncSetAttribute(attn_mma,
                         cudaFuncAttributeMaxDynamicSharedMemorySize, ASMEM);

    const int nX = M_ * H_;
    const int nW = H_ * H_;
    rope_init_kernel<<<S_, 64>>>();
    split_kernel<<<nX / 1024, 256>>>(x, xh, xl, nX);
    round4_kernel<<<dim3(nW / 1024, 4), 256>>>(Wq, Wk, Wv, Wo, wh, nW);

    dim3 gq(H_ / 256, M_ / 64, 3);
    gemm_mma<<<gq, 256, GSMEM>>>(xh, xl, wh, bq, bk, bv,
                                 qh, ql, kh, vh, nullptr, 1);

    attn_mma<<<dim3(S_ / 128, NH_, B_), 256, ASMEM>>>(qh, ql, kh, vh, ah, al);

    dim3 go(H_ / 256, M_ / 64, 1);
    gemm_mma<<<go, 256, GSMEM>>>(ah, al, wh + 3*(size_t)nW,
                                 bo, nullptr, nullptr,
                                 nullptr, nullptr, nullptr, nullptr,
                                 out, 0);
}

// round 10
// speedup vs baseline: 2.2683x; 1.4886x over previous
#include <cuda_runtime.h>
#include <cuda_fp16.h>
#include <math.h>
#include <stdint.h>

#define B_   2
#define S_   2048
#define H_   2048
#define NH_  16
#define D_   128
#define M_   (B_*S_)          // 4096 rows for all GEMMs

// ---------------- scratch (static device globals; no allocation) ------------
__device__ __align__(256) __half g_x[(size_t)M_*H_];         // x, fp16
__device__ __align__(256) __half g_w[(size_t)4*H_*H_];       // Wq,Wk,Wv,Wo fp16
__device__ __align__(256) __half g_a[(size_t)M_*H_];         // attn out fp16
__device__ __align__(256) __half g_q[(size_t)B_*NH_*S_*D_];
__device__ __align__(256) __half g_k[(size_t)B_*NH_*S_*D_];
__device__ __align__(256) __half g_v[(size_t)B_*NH_*S_*D_];
__device__ __align__(256) float2 g_rope[(size_t)S_ * 64];    // (cos, sin)

// =========================== helpers ========================================
__device__ __forceinline__ uint32_t smem_u32(const void* p) {
    uint32_t a;
    asm("{ .reg .u64 t; cvta.to.shared.u64 t, %1; cvt.u32.u64 %0, t; }"
        : "=r"(a) : "l"(p));
    return a;
}
__device__ __forceinline__ void ldsm4(uint32_t& r0, uint32_t& r1,
                                      uint32_t& r2, uint32_t& r3, uint32_t a) {
    asm volatile("ldmatrix.sync.aligned.m8n8.x4.shared.b16 {%0,%1,%2,%3}, [%4];"
                 : "=r"(r0), "=r"(r1), "=r"(r2), "=r"(r3) : "r"(a));
}
__device__ __forceinline__ void ldsm4t(uint32_t& r0, uint32_t& r1,
                                       uint32_t& r2, uint32_t& r3, uint32_t a) {
    asm volatile("ldmatrix.sync.aligned.m8n8.x4.trans.shared.b16 {%0,%1,%2,%3}, [%4];"
                 : "=r"(r0), "=r"(r1), "=r"(r2), "=r"(r3) : "r"(a));
}
// fp16 MMA, fp32 accumulate; non-volatile so ptxas may schedule freely.
__device__ __forceinline__ void mma16816(float* c, const uint32_t* a,
                                         const uint32_t* b) {
    asm("mma.sync.aligned.m16n8k16.row.col.f32.f16.f16.f32 "
        "{%0,%1,%2,%3}, {%4,%5,%6,%7}, {%8,%9}, {%0,%1,%2,%3};"
        : "+f"(c[0]), "+f"(c[1]), "+f"(c[2]), "+f"(c[3])
        : "r"(a[0]), "r"(a[1]), "r"(a[2]), "r"(a[3]), "r"(b[0]), "r"(b[1]));
}
__device__ __forceinline__ float ex2(float x) {
    float r;
    asm("ex2.approx.ftz.f32 %0, %1;" : "=f"(r) : "f"(x));
    return r;
}
__device__ __forceinline__ uint32_t pack2h(float a, float b) {
    __half2 hv = __halves2half2(__float2half_rn(a), __float2half_rn(b));
    return *(uint32_t*)&hv;
}
#define CP_ASYNC(sa, ga) \
    asm volatile("cp.async.cg.shared.global [%0], [%1], 16;" :: "r"(sa), "l"(ga))
#define CP_COMMIT() asm volatile("cp.async.commit_group;" ::: "memory")
#define CP_WAIT0()  asm volatile("cp.async.wait_group 0;" ::: "memory")
#define CP_WAIT1()  asm volatile("cp.async.wait_group 1;" ::: "memory")

// ====================== setup kernels =======================================
__global__ void __launch_bounds__(64)
rope_init_kernel()
{
    int s = blockIdx.x, p = threadIdx.x;
    float inv = expf(-(float)p * 0.14391156831212787f); // ln(10000)/64
    float ang = (float)s * inv;
    float sn, cs;
    sincosf(ang, &sn, &cs);
    g_rope[s * 64 + p] = make_float2(cs, sn);
}

// fp32 -> fp16 (single)
__global__ void __launch_bounds__(256)
round_kernel(const float* __restrict__ src, __half* __restrict__ dst, int n)
{
    int i = (blockIdx.x * 256 + threadIdx.x) * 4;
    if (i >= n) return;
    float4 v = *(const float4*)(src + i);
    __half h[4] = {__float2half_rn(v.x), __float2half_rn(v.y),
                   __float2half_rn(v.z), __float2half_rn(v.w)};
    *(uint2*)(dst + i) = *(uint2*)h;
}

// four weight matrices -> fp16, z selects source
__global__ void __launch_bounds__(256)
round4_kernel(const float* __restrict__ s0, const float* __restrict__ s1,
              const float* __restrict__ s2, const float* __restrict__ s3,
              __half* __restrict__ dst, int n)
{
    const int z = blockIdx.y;
    const float* src = (z == 0) ? s0 : (z == 1) ? s1 : (z == 2) ? s2 : s3;
    int i = (blockIdx.x * 256 + threadIdx.x) * 4;
    if (i >= n) return;
    float4 v = *(const float4*)(src + i);
    __half h[4] = {__float2half_rn(v.x), __float2half_rn(v.y),
                   __float2half_rn(v.z), __float2half_rn(v.w)};
    *(uint2*)(dst + (size_t)z * n + i) = *(uint2*)h;
}

// ================== fp16 tensor-core GEMM (mma.sync path) ===================
// C[M,N] = A[M,K] @ W[N,K]^T + bias, K=2048, all-fp16 operands, fp32 accum.
// Block tile 64(M) x 256(N), 8 warps 2x4, warp tile 32x64, BK=32,
// 2-stage cp.async pipeline, 2 CTAs/SM.
// fused: z=0 Q (RoPE), z=1 K (RoPE), z=2 V. non-fused: fp32 [M,N] out.
#define BKG     32
#define LDSTR   80
#define B_OFF   (64 * LDSTR)             // 5120
#define STG     (B_OFF + 256 * LDSTR)    // 25600
#define GSMEM   (2 * STG)                // 51200

__device__ __forceinline__ void g_load(uint32_t sbase,
    const __half* A0, const __half* B0, int k0, int tid)
{
    {
        int row = tid >> 2, c4 = tid & 3;
        CP_ASYNC(sbase + row * LDSTR + c4 * 16,
                 A0 + (size_t)row * H_ + k0 + c4 * 8);
    }
#pragma unroll
    for (int rep = 0; rep < 4; rep++) {
        int idx = tid + rep * 256;
        int row = idx >> 2, c4 = idx & 3;
        CP_ASYNC(sbase + B_OFF + row * LDSTR + c4 * 16,
                 B0 + (size_t)row * H_ + k0 + c4 * 8);
    }
}

__global__ void __launch_bounds__(256, 2)
gemm_mma(const __half* __restrict__ Ain, const __half* __restrict__ WB,
         const float* __restrict__ b0, const float* __restrict__ b1,
         const float* __restrict__ b2,
         __half* o0, __half* o1, __half* o2,
         float* out, int fused)
{
    extern __shared__ char sm[];
    const uint32_t smb = smem_u32(sm);
    const int tid  = threadIdx.x;
    const int wid  = tid >> 5, lane = tid & 31;
    const int bm   = blockIdx.y * 64, bn = blockIdx.x * 256;
    const int wm   = (wid >> 2) * 32, wn = (wid & 3) * 64;

    const __half* W = WB;
    const float* bias = b0;
    __half* oh = nullptr;
    int mode = 2;                       // 2 = fp32 row-major out
    if (fused) {
        const int z = blockIdx.z;
        W += (size_t)z * H_ * H_;
        bias = (z == 0) ? b0 : (z == 1) ? b1 : b2;
        oh   = (z == 0) ? o0 : (z == 1) ? o1 : o2;
        mode = (z == 2) ? 0 : 1;        // 1 = RoPE+fp16, 0 = fp16
    }

    const __half* A0 = Ain + (size_t)bm * H_;
    const __half* B0 = W   + (size_t)bn * H_;

    float acc[2][8][4];
#pragma unroll
    for (int i = 0; i < 2; i++)
#pragma unroll
        for (int j = 0; j < 8; j++)
#pragma unroll
            for (int q = 0; q < 4; q++) acc[i][j][q] = 0.f;

    const int arow  = (lane & 7) + ((lane >> 3) & 1) * 8;
    const int acoff = ((lane >> 4) & 1) * 16;
    const int krow  = (lane & 7) + ((lane >> 4) & 1) * 8;
    const int kcoff = ((lane >> 3) & 1) * 16;

    g_load(smb, A0, B0, 0, tid);
    CP_COMMIT();

    const int NCH = H_ / BKG;   // 64
    for (int it = 0; it < NCH; it++) {
        if (it + 1 < NCH) {
            g_load(smb + ((it + 1) & 1) * STG, A0, B0, (it + 1) * BKG, tid);
            CP_COMMIT();
            CP_WAIT1();
        } else {
            CP_WAIT0();
        }
        __syncthreads();

        const uint32_t st = smb + (uint32_t)(it & 1) * STG;
#pragma unroll
        for (int ks = 0; ks < 2; ks++) {
            const int kb = ks * 32;
            uint32_t af[2][4];
#pragma unroll
            for (int mi = 0; mi < 2; mi++) {
                uint32_t off = (uint32_t)((wm + mi * 16 + arow) * LDSTR + kb + acoff);
                ldsm4(af[mi][0], af[mi][1], af[mi][2], af[mi][3], st + off);
            }
#pragma unroll
            for (int nq = 0; nq < 4; nq++) {
                uint32_t off = (uint32_t)((wn + nq * 16 + krow) * LDSTR + kb + kcoff);
                uint32_t b4[4];
                ldsm4(b4[0], b4[1], b4[2], b4[3], st + B_OFF + off);
                mma16816(acc[0][2*nq],   af[0], &b4[0]);
                mma16816(acc[1][2*nq],   af[1], &b4[0]);
                mma16816(acc[0][2*nq+1], af[0], &b4[2]);
                mma16816(acc[1][2*nq+1], af[1], &b4[2]);
            }
        }
        __syncthreads();
    }

    // ------------------------------ epilogue --------------------------------
    const int qrow = lane >> 2;
    const int qcol = (lane & 3) * 2;
#pragma unroll
    for (int mi = 0; mi < 2; mi++) {
#pragma unroll
        for (int half_ = 0; half_ < 2; half_++) {
            const int m  = bm + wm + mi * 16 + qrow + half_ * 8;
            const int sI = m & (S_ - 1);
#pragma unroll
            for (int nj = 0; nj < 8; nj++) {
                const int n0 = bn + wn + nj * 8 + qcol;
                float v0 = acc[mi][nj][half_ * 2 + 0] + bias[n0];
                float v1 = acc[mi][nj][half_ * 2 + 1] + bias[n0 + 1];
                if (mode == 1) {
                    int pr = (n0 & (D_ - 1)) >> 1;
                    float2 cssn = g_rope[sI * 64 + pr];
                    float e = v0, o = v1;
                    v0 = e * cssn.x - o * cssn.y;
                    v1 = o * cssn.x + e * cssn.y;
                }
                if (mode == 2) {
                    *(float2*)(out + (size_t)m * H_ + n0) = make_float2(v0, v1);
                } else {
                    int b = m >> 11;
                    int h = n0 >> 7;
                    int dd = n0 & (D_ - 1);
                    size_t idx = (((size_t)(b * NH_ + h) * S_ + sI) << 7) + dd;
                    *(uint32_t*)(oh + idx) = pack2h(v0, v1);
                }
            }
        }
    }
}

// ================= causal flash attention on tensor cores ===================
// 128 queries/block, 64-key tiles, 8 warps. Q fragments in registers.
// K, V single fp16 in smem; P single fp16 in registers.
// 3-stage cp.async pipeline, single barrier per tile.
#define KSTR  272
#define ARRB  (64 * KSTR)             // 17408
#define STGB  (2 * ARRB)              // K, V per stage: 34816
#define ASMEM (3 * STGB)              // 104448

__device__ __forceinline__ void load_kv(uint32_t sb,
    const __half* kh, const __half* vh, size_t toff, int tid)
{
    const __half* srcs[2] = {kh + toff, vh + toff};
#pragma unroll
    for (int arr = 0; arr < 2; arr++)
#pragma unroll
        for (int rep = 0; rep < 4; rep++) {
            int ch = tid + rep * 256;
            int row = ch >> 4, c = ch & 15;
            CP_ASYNC(sb + arr * ARRB + row * KSTR + c * 16,
                     srcs[arr] + row * D_ + c * 8);
        }
}

__global__ void __launch_bounds__(256, 1)
attn_mma(const __half* __restrict__ Qg, const __half* __restrict__ Kg,
         const __half* __restrict__ Vg, __half* __restrict__ Og)
{
    extern __shared__ char sm[];
    const uint32_t smb = smem_u32(sm);
    const int tid = threadIdx.x, wid = tid >> 5, lane = tid & 31;
    const int qt = blockIdx.x, h = blockIdx.y, b = blockIdx.z;
    const int bh = b * NH_ + h;
    const size_t qoff = ((size_t)bh * S_ + qt * 128) * D_;
    const __half* kb = Kg + (size_t)bh * S_ * D_;
    const __half* vb = Vg + (size_t)bh * S_ * D_;

    // ---- stage Q into slot0; extract fragments to registers ----------------
#pragma unroll
    for (int rep = 0; rep < 8; rep++) {
        int ch = tid + rep * 256;
        int row = ch >> 4, c = ch & 15;
        CP_ASYNC(smb + row * KSTR + c * 16, Qg + qoff + row * D_ + c * 8);
    }
    CP_COMMIT(); CP_WAIT0();
    __syncthreads();

    const int arow  = (lane & 7) + ((lane >> 3) & 1) * 8;
    const int acoff = ((lane >> 4) & 1) * 16;
    uint32_t qf[8][4];
#pragma unroll
    for (int kk = 0; kk < 8; kk++) {
        uint32_t off = (uint32_t)((wid * 16 + arow) * KSTR + kk * 32 + acoff);
        ldsm4(qf[kk][0], qf[kk][1], qf[kk][2], qf[kk][3], smb + off);
    }
    __syncthreads();   // Q staging area free for K/V

    const int NT = 2 * qt + 2;

    load_kv(smb,        kb, vb, 0,               tid); CP_COMMIT();
    load_kv(smb + STGB, kb, vb, (size_t)64 * D_, tid); CP_COMMIT();

    float o[16][4];
#pragma unroll
    for (int nt = 0; nt < 16; nt++)
#pragma unroll
        for (int c = 0; c < 4; c++) o[nt][c] = 0.f;
    float mrow[2] = {-1e30f, -1e30f}, lrow[2] = {0.f, 0.f};
    const float CSc = 0.12752551286084458f;   // log2(e)/sqrt(128)

    const int krow  = (lane & 7) + ((lane >> 4) & 1) * 8;
    const int kcoff = ((lane >> 3) & 1) * 16;

    for (int it = 0; it < NT; it++) {
        if (it == NT - 1) { CP_WAIT0(); } else { CP_WAIT1(); }
        __syncthreads();
        const uint32_t st = smb + (uint32_t)(it % 3) * STGB;

        // ---------------- S = Q @ K^T ---------------------------------------
        float s[8][4];
#pragma unroll
        for (int nj = 0; nj < 8; nj++)
#pragma unroll
            for (int c = 0; c < 4; c++) s[nj][c] = 0.f;

#pragma unroll
        for (int kk = 0; kk < 8; kk++) {
#pragma unroll
            for (int g = 0; g < 4; g++) {
                uint32_t off = (uint32_t)((g * 16 + krow) * KSTR + kk * 32 + kcoff);
                uint32_t k4[4];
                ldsm4(k4[0], k4[1], k4[2], k4[3], st + off);
                mma16816(s[2*g],   qf[kk], &k4[0]);
                mma16816(s[2*g+1], qf[kk], &k4[2]);
            }
        }

        // ---------------- causal mask (last two tiles only) -----------------
        if (it >= 2 * qt) {
            const int q0r = qt * 128 + wid * 16 + (lane >> 2);
            const int kc  = it * 64 + (lane & 3) * 2;
#pragma unroll
            for (int nj = 0; nj < 8; nj++) {
                int kcol = kc + nj * 8;
                if (kcol     > q0r)     s[nj][0] = -1e30f;
                if (kcol + 1 > q0r)     s[nj][1] = -1e30f;
                if (kcol     > q0r + 8) s[nj][2] = -1e30f;
                if (kcol + 1 > q0r + 8) s[nj][3] = -1e30f;
            }
        }

        // ---------------- online softmax ------------------------------------
        float tm0 = -1e30f, tm1 = -1e30f;
#pragma unroll
        for (int nj = 0; nj < 8; nj++) {
            tm0 = fmaxf(tm0, fmaxf(s[nj][0], s[nj][1]));
            tm1 = fmaxf(tm1, fmaxf(s[nj][2], s[nj][3]));
        }
        tm0 = fmaxf(tm0, __shfl_xor_sync(0xffffffffu, tm0, 1));
        tm0 = fmaxf(tm0, __shfl_xor_sync(0xffffffffu, tm0, 2));
        tm1 = fmaxf(tm1, __shfl_xor_sync(0xffffffffu, tm1, 1));
        tm1 = fmaxf(tm1, __shfl_xor_sync(0xffffffffu, tm1, 2));
        float mn0 = fmaxf(mrow[0], tm0), mn1 = fmaxf(mrow[1], tm1);
        float cor0 = ex2(CSc * (mrow[0] - mn0));
        float cor1 = ex2(CSc * (mrow[1] - mn1));
        mrow[0] = mn0; mrow[1] = mn1;
        float rs0 = 0.f, rs1 = 0.f;
#pragma unroll
        for (int nj = 0; nj < 8; nj++) {
            s[nj][0] = ex2(CSc * (s[nj][0] - mn0)); rs0 += s[nj][0];
            s[nj][1] = ex2(CSc * (s[nj][1] - mn0)); rs0 += s[nj][1];
            s[nj][2] = ex2(CSc * (s[nj][2] - mn1)); rs1 += s[nj][2];
            s[nj][3] = ex2(CSc * (s[nj][3] - mn1)); rs1 += s[nj][3];
        }
        rs0 += __shfl_xor_sync(0xffffffffu, rs0, 1);
        rs0 += __shfl_xor_sync(0xffffffffu, rs0, 2);
        rs1 += __shfl_xor_sync(0xffffffffu, rs1, 1);
        rs1 += __shfl_xor_sync(0xffffffffu, rs1, 2);
        lrow[0] = lrow[0] * cor0 + rs0;
        lrow[1] = lrow[1] * cor1 + rs1;
#pragma unroll
        for (int nt = 0; nt < 16; nt++) {
            o[nt][0] *= cor0; o[nt][1] *= cor0;
            o[nt][2] *= cor1; o[nt][3] *= cor1;
        }

        // ---------------- P -> fp16 a-frags (registers only) ----------------
        uint32_t pf[4][4];
#pragma unroll
        for (int t = 0; t < 4; t++) {
            pf[t][0] = pack2h(s[2*t][0],   s[2*t][1]);
            pf[t][1] = pack2h(s[2*t][2],   s[2*t][3]);
            pf[t][2] = pack2h(s[2*t+1][0], s[2*t+1][1]);
            pf[t][3] = pack2h(s[2*t+1][2], s[2*t+1][3]);
        }

        // ---------------- O += P @ V ----------------------------------------
#pragma unroll
        for (int t = 0; t < 4; t++) {
#pragma unroll
            for (int nc = 0; nc < 8; nc++) {
                uint32_t off = (uint32_t)((t * 16 + arow) * KSTR + nc * 32 + acoff);
                uint32_t v4[4];
                ldsm4t(v4[0], v4[1], v4[2], v4[3], st + ARRB + off);
                mma16816(o[2*nc],   pf[t], &v4[0]);
                mma16816(o[2*nc+1], pf[t], &v4[2]);
            }
        }

        if (it + 2 < NT) {
            load_kv(smb + (uint32_t)((it + 2) % 3) * STGB,
                    kb, vb, (size_t)(it + 2) * 64 * D_, tid);
            CP_COMMIT();
        }
    }

    // ---------------- epilogue: O/l -> fp16, [b*s, h*d] ---------------------
    const float inv0 = 1.f / lrow[0], inv1 = 1.f / lrow[1];
    const int q0 = qt * 128 + wid * 16 + (lane >> 2);
    const size_t base0 = ((size_t)(b * S_) + q0) * H_ + h * 128;
    const size_t base1 = base0 + (size_t)8 * H_;
#pragma unroll
    for (int nt = 0; nt < 16; nt++) {
        const int col = nt * 8 + (lane & 3) * 2;
        *(uint32_t*)(Og + base0 + col) = pack2h(o[nt][0] * inv0, o[nt][1] * inv0);
        *(uint32_t*)(Og + base1 + col) = pack2h(o[nt][2] * inv1, o[nt][3] * inv1);
    }
}

// ============================================================================
extern "C" void kernel_launch(void* const* d_in, const int* in_sizes, int n_in,
                              void* d_out, int out_size)
{
    const float* x  = (const float*)d_in[0];
    const float* Wq = (const float*)d_in[1];
    const float* bq = (const float*)d_in[2];
    const float* Wk = (const float*)d_in[3];
    const float* bk = (const float*)d_in[4];
    const float* Wv = (const float*)d_in[5];
    const float* bv = (const float*)d_in[6];
    const float* Wo = (const float*)d_in[7];
    const float* bo = (const float*)d_in[8];
    float* out = (float*)d_out;

    __half *xp, *wp, *ap, *qp, *kp, *vp;
    cudaGetSymbolAddress((void**)&xp, g_x);
    cudaGetSymbolAddress((void**)&wp, g_w);
    cudaGetSymbolAddress((void**)&ap, g_a);
    cudaGetSymbolAddress((void**)&qp, g_q);
    cudaGetSymbolAddress((void**)&kp, g_k);
    cudaGetSymbolAddress((void**)&vp, g_v);

    cudaFuncSetAttribute(gemm_mma,
                         cudaFuncAttributeMaxDynamicSharedMemorySize, GSMEM);
    cudaFuncSetAttribute(attn_mma,
                         cudaFuncAttributeMaxDynamicSharedMemorySize, ASMEM);

    const int nX = M_ * H_;
    const int nW = H_ * H_;
    rope_init_kernel<<<S_, 64>>>();
    round_kernel<<<nX / 1024, 256>>>(x, xp, nX);
    round4_kernel<<<dim3(nW / 1024, 4), 256>>>(Wq, Wk, Wv, Wo, wp, nW);

    dim3 gq(H_ / 256, M_ / 64, 3);
    gemm_mma<<<gq, 256, GSMEM>>>(xp, wp, bq, bk, bv,
                                 qp, kp, vp, nullptr, 1);

    attn_mma<<<dim3(S_ / 128, NH_, B_), 256, ASMEM>>>(qp, kp, vp, ap);

    dim3 go(H_ / 256, M_ / 64, 1);
    gemm_mma<<<go, 256, GSMEM>>>(ap, wp + 3*(size_t)nW,
                                 bo, nullptr, nullptr,
                                 nullptr, nullptr, nullptr,
                                 out, 0);
}

// round 11
// speedup vs baseline: 2.4014x; 1.0587x over previous
#include <cuda_runtime.h>
#include <cuda_fp16.h>
#include <math.h>
#include <stdint.h>

#define B_   2
#define S_   2048
#define H_   2048
#define NH_  16
#define D_   128
#define M_   (B_*S_)          // 4096 rows for all GEMMs

// ---------------- scratch (static device globals; no allocation) ------------
__device__ __align__(256) __half g_x[(size_t)M_*H_];         // x, fp16
__device__ __align__(256) __half g_w[(size_t)4*H_*H_];       // Wq,Wk,Wv,Wo fp16
__device__ __align__(256) __half g_a[(size_t)M_*H_];         // attn out fp16
__device__ __align__(256) __half g_q[(size_t)B_*NH_*S_*D_];
__device__ __align__(256) __half g_k[(size_t)B_*NH_*S_*D_];
__device__ __align__(256) __half g_v[(size_t)B_*NH_*S_*D_];
__device__ __align__(256) float2 g_rope[(size_t)S_ * 64];    // (cos, sin)

// =========================== helpers ========================================
__device__ __forceinline__ uint32_t smem_u32(const void* p) {
    uint32_t a;
    asm("{ .reg .u64 t; cvta.to.shared.u64 t, %1; cvt.u32.u64 %0, t; }"
        : "=r"(a) : "l"(p));
    return a;
}
__device__ __forceinline__ void ldsm4(uint32_t& r0, uint32_t& r1,
                                      uint32_t& r2, uint32_t& r3, uint32_t a) {
    asm volatile("ldmatrix.sync.aligned.m8n8.x4.shared.b16 {%0,%1,%2,%3}, [%4];"
                 : "=r"(r0), "=r"(r1), "=r"(r2), "=r"(r3) : "r"(a));
}
__device__ __forceinline__ void ldsm4t(uint32_t& r0, uint32_t& r1,
                                       uint32_t& r2, uint32_t& r3, uint32_t a) {
    asm volatile("ldmatrix.sync.aligned.m8n8.x4.trans.shared.b16 {%0,%1,%2,%3}, [%4];"
                 : "=r"(r0), "=r"(r1), "=r"(r2), "=r"(r3) : "r"(a));
}
// fp16 MMA, fp32 accumulate; non-volatile so ptxas may schedule freely.
__device__ __forceinline__ void mma16816(float* c, const uint32_t* a,
                                         const uint32_t* b) {
    asm("mma.sync.aligned.m16n8k16.row.col.f32.f16.f16.f32 "
        "{%0,%1,%2,%3}, {%4,%5,%6,%7}, {%8,%9}, {%0,%1,%2,%3};"
        : "+f"(c[0]), "+f"(c[1]), "+f"(c[2]), "+f"(c[3])
        : "r"(a[0]), "r"(a[1]), "r"(a[2]), "r"(a[3]), "r"(b[0]), "r"(b[1]));
}
__device__ __forceinline__ float ex2(float x) {
    float r;
    asm("ex2.approx.ftz.f32 %0, %1;" : "=f"(r) : "f"(x));
    return r;
}
__device__ __forceinline__ uint32_t pack2h(float a, float b) {
    __half2 hv = __halves2half2(__float2half_rn(a), __float2half_rn(b));
    return *(uint32_t*)&hv;
}
#define CP_ASYNC(sa, ga) \
    asm volatile("cp.async.cg.shared.global [%0], [%1], 16;" :: "r"(sa), "l"(ga))
#define CP_COMMIT() asm volatile("cp.async.commit_group;" ::: "memory")
#define CP_WAIT0()  asm volatile("cp.async.wait_group 0;" ::: "memory")
#define CP_WAIT1()  asm volatile("cp.async.wait_group 1;" ::: "memory")

// ====================== setup kernels =======================================
__global__ void __launch_bounds__(64)
rope_init_kernel()
{
    int s = blockIdx.x, p = threadIdx.x;
    float inv = expf(-(float)p * 0.14391156831212787f); // ln(10000)/64
    float ang = (float)s * inv;
    float sn, cs;
    sincosf(ang, &sn, &cs);
    g_rope[s * 64 + p] = make_float2(cs, sn);
}

// fp32 -> fp16 (single)
__global__ void __launch_bounds__(256)
round_kernel(const float* __restrict__ src, __half* __restrict__ dst, int n)
{
    int i = (blockIdx.x * 256 + threadIdx.x) * 4;
    if (i >= n) return;
    float4 v = *(const float4*)(src + i);
    __half h[4] = {__float2half_rn(v.x), __float2half_rn(v.y),
                   __float2half_rn(v.z), __float2half_rn(v.w)};
    *(uint2*)(dst + i) = *(uint2*)h;
}

// four weight matrices -> fp16, z selects source
__global__ void __launch_bounds__(256)
round4_kernel(const float* __restrict__ s0, const float* __restrict__ s1,
              const float* __restrict__ s2, const float* __restrict__ s3,
              __half* __restrict__ dst, int n)
{
    const int z = blockIdx.y;
    const float* src = (z == 0) ? s0 : (z == 1) ? s1 : (z == 2) ? s2 : s3;
    int i = (blockIdx.x * 256 + threadIdx.x) * 4;
    if (i >= n) return;
    float4 v = *(const float4*)(src + i);
    __half h[4] = {__float2half_rn(v.x), __float2half_rn(v.y),
                   __float2half_rn(v.z), __float2half_rn(v.w)};
    *(uint2*)(dst + (size_t)z * n + i) = *(uint2*)h;
}

// ================== fp16 tensor-core GEMM (mma.sync path) ===================
// C[M,N] = A[M,K] @ W[N,K]^T + bias, K=2048, all-fp16, fp32 accum.
// Block tile 128(M) x 256(N), 8 warps 2x4, warp tile 64x64 (mi=4), BK=32,
// 3-stage cp.async pipeline, single barrier per chunk, MMA:LDSM = 4:1.
// fused: z=0 Q (RoPE), z=1 K (RoPE), z=2 V. non-fused: fp32 [M,N] out.
#define BKG     32
#define LDSTR   80
#define B_OFF   (128 * LDSTR)            // 10240
#define STG     (B_OFF + 256 * LDSTR)    // 30720
#define GSMEM   (3 * STG)                // 92160

__device__ __forceinline__ void g_load(uint32_t sbase,
    const __half* A0, const __half* B0, int k0, int tid)
{
#pragma unroll
    for (int rep = 0; rep < 2; rep++) {      // A: 128 rows x 4 chunks = 512
        int idx = tid + rep * 256;
        int row = idx >> 2, c4 = idx & 3;
        CP_ASYNC(sbase + row * LDSTR + c4 * 16,
                 A0 + (size_t)row * H_ + k0 + c4 * 8);
    }
#pragma unroll
    for (int rep = 0; rep < 4; rep++) {      // B: 256 rows x 4 chunks = 1024
        int idx = tid + rep * 256;
        int row = idx >> 2, c4 = idx & 3;
        CP_ASYNC(sbase + B_OFF + row * LDSTR + c4 * 16,
                 B0 + (size_t)row * H_ + k0 + c4 * 8);
    }
}

__global__ void __launch_bounds__(256, 1)
gemm_mma(const __half* __restrict__ Ain, const __half* __restrict__ WB,
         const float* __restrict__ b0, const float* __restrict__ b1,
         const float* __restrict__ b2,
         __half* o0, __half* o1, __half* o2,
         float* out, int fused)
{
    extern __shared__ char sm[];
    const uint32_t smb = smem_u32(sm);
    const int tid  = threadIdx.x;
    const int wid  = tid >> 5, lane = tid & 31;
    const int bm   = blockIdx.y * 128, bn = blockIdx.x * 256;
    const int wm   = (wid >> 2) * 64, wn = (wid & 3) * 64;

    const __half* W = WB;
    const float* bias = b0;
    __half* oh = nullptr;
    int mode = 2;                       // 2 = fp32 row-major out
    if (fused) {
        const int z = blockIdx.z;
        W += (size_t)z * H_ * H_;
        bias = (z == 0) ? b0 : (z == 1) ? b1 : b2;
        oh   = (z == 0) ? o0 : (z == 1) ? o1 : o2;
        mode = (z == 2) ? 0 : 1;        // 1 = RoPE+fp16, 0 = fp16
    }

    const __half* A0 = Ain + (size_t)bm * H_;
    const __half* B0 = W   + (size_t)bn * H_;

    float acc[4][8][4];
#pragma unroll
    for (int i = 0; i < 4; i++)
#pragma unroll
        for (int j = 0; j < 8; j++)
#pragma unroll
            for (int q = 0; q < 4; q++) acc[i][j][q] = 0.f;

    const int arow  = (lane & 7) + ((lane >> 3) & 1) * 8;
    const int acoff = ((lane >> 4) & 1) * 16;
    const int krow  = (lane & 7) + ((lane >> 4) & 1) * 8;
    const int kcoff = ((lane >> 3) & 1) * 16;

    g_load(smb,       A0, B0, 0,   tid); CP_COMMIT();
    g_load(smb + STG, A0, B0, BKG, tid); CP_COMMIT();

    const int NCH = H_ / BKG;   // 64
    for (int it = 0; it < NCH; it++) {
        if (it == NCH - 1) { CP_WAIT0(); } else { CP_WAIT1(); }
        __syncthreads();

        const uint32_t st = smb + (uint32_t)(it % 3) * STG;
#pragma unroll
        for (int ks = 0; ks < 2; ks++) {
            const int kb = ks * 32;
            uint32_t af[4][4];
#pragma unroll
            for (int mi = 0; mi < 4; mi++) {
                uint32_t off = (uint32_t)((wm + mi * 16 + arow) * LDSTR + kb + acoff);
                ldsm4(af[mi][0], af[mi][1], af[mi][2], af[mi][3], st + off);
            }
#pragma unroll
            for (int nq = 0; nq < 4; nq++) {
                uint32_t off = (uint32_t)((wn + nq * 16 + krow) * LDSTR + kb + kcoff);
                uint32_t b4[4];
                ldsm4(b4[0], b4[1], b4[2], b4[3], st + B_OFF + off);
#pragma unroll
                for (int mi = 0; mi < 4; mi++)
                    mma16816(acc[mi][2*nq],   af[mi], &b4[0]);
#pragma unroll
                for (int mi = 0; mi < 4; mi++)
                    mma16816(acc[mi][2*nq+1], af[mi], &b4[2]);
            }
        }
        if (it + 2 < NCH) {
            g_load(smb + (uint32_t)((it + 2) % 3) * STG, A0, B0,
                   (it + 2) * BKG, tid);
            CP_COMMIT();
        }
    }

    // ------------------------------ epilogue --------------------------------
    const int qrow = lane >> 2;
    const int qcol = (lane & 3) * 2;
#pragma unroll
    for (int mi = 0; mi < 4; mi++) {
#pragma unroll
        for (int half_ = 0; half_ < 2; half_++) {
            const int m  = bm + wm + mi * 16 + qrow + half_ * 8;
            const int sI = m & (S_ - 1);
#pragma unroll
            for (int nj = 0; nj < 8; nj++) {
                const int n0 = bn + wn + nj * 8 + qcol;
                float v0 = acc[mi][nj][half_ * 2 + 0] + bias[n0];
                float v1 = acc[mi][nj][half_ * 2 + 1] + bias[n0 + 1];
                if (mode == 1) {
                    int pr = (n0 & (D_ - 1)) >> 1;
                    float2 cssn = g_rope[sI * 64 + pr];
                    float e = v0, o = v1;
                    v0 = e * cssn.x - o * cssn.y;
                    v1 = o * cssn.x + e * cssn.y;
                }
                if (mode == 2) {
                    *(float2*)(out + (size_t)m * H_ + n0) = make_float2(v0, v1);
                } else {
                    int b = m >> 11;
                    int h = n0 >> 7;
                    int dd = n0 & (D_ - 1);
                    size_t idx = (((size_t)(b * NH_ + h) * S_ + sI) << 7) + dd;
                    *(uint32_t*)(oh + idx) = pack2h(v0, v1);
                }
            }
        }
    }
}

// ================= causal flash attention on tensor cores ===================
// 128 queries/block, 64-key tiles, 8 warps. Q fragments in registers.
// K, V single fp16 in smem; P single fp16 in registers.
// 3-stage cp.async pipeline, single barrier per tile.  (unchanged from R10)
#define KSTR  272
#define ARRB  (64 * KSTR)             // 17408
#define STGB  (2 * ARRB)              // K, V per stage: 34816
#define ASMEM (3 * STGB)              // 104448

__device__ __forceinline__ void load_kv(uint32_t sb,
    const __half* kh, const __half* vh, size_t toff, int tid)
{
    const __half* srcs[2] = {kh + toff, vh + toff};
#pragma unroll
    for (int arr = 0; arr < 2; arr++)
#pragma unroll
        for (int rep = 0; rep < 4; rep++) {
            int ch = tid + rep * 256;
            int row = ch >> 4, c = ch & 15;
            CP_ASYNC(sb + arr * ARRB + row * KSTR + c * 16,
                     srcs[arr] + row * D_ + c * 8);
        }
}

__global__ void __launch_bounds__(256, 1)
attn_mma(const __half* __restrict__ Qg, const __half* __restrict__ Kg,
         const __half* __restrict__ Vg, __half* __restrict__ Og)
{
    extern __shared__ char sm[];
    const uint32_t smb = smem_u32(sm);
    const int tid = threadIdx.x, wid = tid >> 5, lane = tid & 31;
    const int qt = blockIdx.x, h = blockIdx.y, b = blockIdx.z;
    const int bh = b * NH_ + h;
    const size_t qoff = ((size_t)bh * S_ + qt * 128) * D_;
    const __half* kb = Kg + (size_t)bh * S_ * D_;
    const __half* vb = Vg + (size_t)bh * S_ * D_;

#pragma unroll
    for (int rep = 0; rep < 8; rep++) {
        int ch = tid + rep * 256;
        int row = ch >> 4, c = ch & 15;
        CP_ASYNC(smb + row * KSTR + c * 16, Qg + qoff + row * D_ + c * 8);
    }
    CP_COMMIT(); CP_WAIT0();
    __syncthreads();

    const int arow  = (lane & 7) + ((lane >> 3) & 1) * 8;
    const int acoff = ((lane >> 4) & 1) * 16;
    uint32_t qf[8][4];
#pragma unroll
    for (int kk = 0; kk < 8; kk++) {
        uint32_t off = (uint32_t)((wid * 16 + arow) * KSTR + kk * 32 + acoff);
        ldsm4(qf[kk][0], qf[kk][1], qf[kk][2], qf[kk][3], smb + off);
    }
    __syncthreads();   // Q staging area free for K/V

    const int NT = 2 * qt + 2;

    load_kv(smb,        kb, vb, 0,               tid); CP_COMMIT();
    load_kv(smb + STGB, kb, vb, (size_t)64 * D_, tid); CP_COMMIT();

    float o[16][4];
#pragma unroll
    for (int nt = 0; nt < 16; nt++)
#pragma unroll
        for (int c = 0; c < 4; c++) o[nt][c] = 0.f;
    float mrow[2] = {-1e30f, -1e30f}, lrow[2] = {0.f, 0.f};
    const float CSc = 0.12752551286084458f;   // log2(e)/sqrt(128)

    const int krow  = (lane & 7) + ((lane >> 4) & 1) * 8;
    const int kcoff = ((lane >> 3) & 1) * 16;

    for (int it = 0; it < NT; it++) {
        if (it == NT - 1) { CP_WAIT0(); } else { CP_WAIT1(); }
        __syncthreads();
        const uint32_t st = smb + (uint32_t)(it % 3) * STGB;

        float s[8][4];
#pragma unroll
        for (int nj = 0; nj < 8; nj++)
#pragma unroll
            for (int c = 0; c < 4; c++) s[nj][c] = 0.f;

#pragma unroll
        for (int kk = 0; kk < 8; kk++) {
#pragma unroll
            for (int g = 0; g < 4; g++) {
                uint32_t off = (uint32_t)((g * 16 + krow) * KSTR + kk * 32 + kcoff);
                uint32_t k4[4];
                ldsm4(k4[0], k4[1], k4[2], k4[3], st + off);
                mma16816(s[2*g],   qf[kk], &k4[0]);
                mma16816(s[2*g+1], qf[kk], &k4[2]);
            }
        }

        if (it >= 2 * qt) {
            const int q0r = qt * 128 + wid * 16 + (lane >> 2);
            const int kc  = it * 64 + (lane & 3) * 2;
#pragma unroll
            for (int nj = 0; nj < 8; nj++) {
                int kcol = kc + nj * 8;
                if (kcol     > q0r)     s[nj][0] = -1e30f;
                if (kcol + 1 > q0r)     s[nj][1] = -1e30f;
                if (kcol     > q0r + 8) s[nj][2] = -1e30f;
                if (kcol + 1 > q0r + 8) s[nj][3] = -1e30f;
            }
        }

        float tm0 = -1e30f, tm1 = -1e30f;
#pragma unroll
        for (int nj = 0; nj < 8; nj++) {
            tm0 = fmaxf(tm0, fmaxf(s[nj][0], s[nj][1]));
            tm1 = fmaxf(tm1, fmaxf(s[nj][2], s[nj][3]));
        }
        tm0 = fmaxf(tm0, __shfl_xor_sync(0xffffffffu, tm0, 1));
        tm0 = fmaxf(tm0, __shfl_xor_sync(0xffffffffu, tm0, 2));
        tm1 = fmaxf(tm1, __shfl_xor_sync(0xffffffffu, tm1, 1));
        tm1 = fmaxf(tm1, __shfl_xor_sync(0xffffffffu, tm1, 2));
        float mn0 = fmaxf(mrow[0], tm0), mn1 = fmaxf(mrow[1], tm1);
        float cor0 = ex2(CSc * (mrow[0] - mn0));
        float cor1 = ex2(CSc * (mrow[1] - mn1));
        mrow[0] = mn0; mrow[1] = mn1;
        float rs0 = 0.f, rs1 = 0.f;
#pragma unroll
        for (int nj = 0; nj < 8; nj++) {
            s[nj][0] = ex2(CSc * (s[nj][0] - mn0)); rs0 += s[nj][0];
            s[nj][1] = ex2(CSc * (s[nj][1] - mn0)); rs0 += s[nj][1];
            s[nj][2] = ex2(CSc * (s[nj][2] - mn1)); rs1 += s[nj][2];
            s[nj][3] = ex2(CSc * (s[nj][3] - mn1)); rs1 += s[nj][3];
        }
        rs0 += __shfl_xor_sync(0xffffffffu, rs0, 1);
        rs0 += __shfl_xor_sync(0xffffffffu, rs0, 2);
        rs1 += __shfl_xor_sync(0xffffffffu, rs1, 1);
        rs1 += __shfl_xor_sync(0xffffffffu, rs1, 2);
        lrow[0] = lrow[0] * cor0 + rs0;
        lrow[1] = lrow[1] * cor1 + rs1;
#pragma unroll
        for (int nt = 0; nt < 16; nt++) {
            o[nt][0] *= cor0; o[nt][1] *= cor0;
            o[nt][2] *= cor1; o[nt][3] *= cor1;
        }

        uint32_t pf[4][4];
#pragma unroll
        for (int t = 0; t < 4; t++) {
            pf[t][0] = pack2h(s[2*t][0],   s[2*t][1]);
            pf[t][1] = pack2h(s[2*t][2],   s[2*t][3]);
            pf[t][2] = pack2h(s[2*t+1][0], s[2*t+1][1]);
            pf[t][3] = pack2h(s[2*t+1][2], s[2*t+1][3]);
        }

#pragma unroll
        for (int t = 0; t < 4; t++) {
#pragma unroll
            for (int nc = 0; nc < 8; nc++) {
                uint32_t off = (uint32_t)((t * 16 + arow) * KSTR + nc * 32 + acoff);
                uint32_t v4[4];
                ldsm4t(v4[0], v4[1], v4[2], v4[3], st + ARRB + off);
                mma16816(o[2*nc],   pf[t], &v4[0]);
                mma16816(o[2*nc+1], pf[t], &v4[2]);
            }
        }

        if (it + 2 < NT) {
            load_kv(smb + (uint32_t)((it + 2) % 3) * STGB,
                    kb, vb, (size_t)(it + 2) * 64 * D_, tid);
            CP_COMMIT();
        }
    }

    const float inv0 = 1.f / lrow[0], inv1 = 1.f / lrow[1];
    const int q0 = qt * 128 + wid * 16 + (lane >> 2);
    const size_t base0 = ((size_t)(b * S_) + q0) * H_ + h * 128;
    const size_t base1 = base0 + (size_t)8 * H_;
#pragma unroll
    for (int nt = 0; nt < 16; nt++) {
        const int col = nt * 8 + (lane & 3) * 2;
        *(uint32_t*)(Og + base0 + col) = pack2h(o[nt][0] * inv0, o[nt][1] * inv0);
        *(uint32_t*)(Og + base1 + col) = pack2h(o[nt][2] * inv1, o[nt][3] * inv1);
    }
}

// ============================================================================
extern "C" void kernel_launch(void* const* d_in, const int* in_sizes, int n_in,
                              void* d_out, int out_size)
{
    const float* x  = (const float*)d_in[0];
    const float* Wq = (const float*)d_in[1];
    const float* bq = (const float*)d_in[2];
    const float* Wk = (const float*)d_in[3];
    const float* bk = (const float*)d_in[4];
    const float* Wv = (const float*)d_in[5];
    const float* bv = (const float*)d_in[6];
    const float* Wo = (const float*)d_in[7];
    const float* bo = (const float*)d_in[8];
    float* out = (float*)d_out;

    __half *xp, *wp, *ap, *qp, *kp, *vp;
    cudaGetSymbolAddress((void**)&xp, g_x);
    cudaGetSymbolAddress((void**)&wp, g_w);
    cudaGetSymbolAddress((void**)&ap, g_a);
    cudaGetSymbolAddress((void**)&qp, g_q);
    cudaGetSymbolAddress((void**)&kp, g_k);
    cudaGetSymbolAddress((void**)&vp, g_v);

    cudaFuncSetAttribute(gemm_mma,
                         cudaFuncAttributeMaxDynamicSharedMemorySize, GSMEM);
    cudaFuncSetAttribute(attn_mma,
                         cudaFuncAttributeMaxDynamicSharedMemorySize, ASMEM);

    const int nX = M_ * H_;
    const int nW = H_ * H_;
    rope_init_kernel<<<S_, 64>>>();
    round_kernel<<<nX / 1024, 256>>>(x, xp, nX);
    round4_kernel<<<dim3(nW / 1024, 4), 256>>>(Wq, Wk, Wv, Wo, wp, nW);

    dim3 gq(H_ / 256, M_ / 128, 3);
    gemm_mma<<<gq, 256, GSMEM>>>(xp, wp, bq, bk, bv,
                                 qp, kp, vp, nullptr, 1);

    attn_mma<<<dim3(S_ / 128, NH_, B_), 256, ASMEM>>>(qp, kp, vp, ap);

    dim3 go(H_ / 256, M_ / 128, 1);
    gemm_mma<<<go, 256, GSMEM>>>(ap, wp + 3*(size_t)nW,
                                 bo, nullptr, nullptr,
                                 nullptr, nullptr, nullptr,
                                 out, 0);
}

// round 12
// speedup vs baseline: 2.5623x; 1.0670x over previous
#include <cuda_runtime.h>
#include <cuda_fp16.h>
#include <math.h>
#include <stdint.h>

#define B_   2
#define S_   2048
#define H_   2048
#define NH_  16
#define D_   128
#define M_   (B_*S_)          // 4096 rows for all GEMMs

// ---------------- scratch (static device globals; no allocation) ------------
__device__ __align__(256) __half g_x[(size_t)M_*H_];         // x, fp16
__device__ __align__(256) __half g_w[(size_t)4*H_*H_];       // Wq,Wk,Wv,Wo fp16
__device__ __align__(256) __half g_a[(size_t)M_*H_];         // attn out fp16
__device__ __align__(256) __half g_q[(size_t)B_*NH_*S_*D_];
__device__ __align__(256) __half g_k[(size_t)B_*NH_*S_*D_];
__device__ __align__(256) __half g_v[(size_t)B_*NH_*S_*D_];
__device__ __align__(256) float2 g_rope[(size_t)S_ * 64];    // (cos, sin)

// =========================== helpers ========================================
__device__ __forceinline__ uint32_t smem_u32(const void* p) {
    uint32_t a;
    asm("{ .reg .u64 t; cvta.to.shared.u64 t, %1; cvt.u32.u64 %0, t; }"
        : "=r"(a) : "l"(p));
    return a;
}
__device__ __forceinline__ void ldsm4(uint32_t& r0, uint32_t& r1,
                                      uint32_t& r2, uint32_t& r3, uint32_t a) {
    asm volatile("ldmatrix.sync.aligned.m8n8.x4.shared.b16 {%0,%1,%2,%3}, [%4];"
                 : "=r"(r0), "=r"(r1), "=r"(r2), "=r"(r3) : "r"(a));
}
__device__ __forceinline__ void ldsm4t(uint32_t& r0, uint32_t& r1,
                                       uint32_t& r2, uint32_t& r3, uint32_t a) {
    asm volatile("ldmatrix.sync.aligned.m8n8.x4.trans.shared.b16 {%0,%1,%2,%3}, [%4];"
                 : "=r"(r0), "=r"(r1), "=r"(r2), "=r"(r3) : "r"(a));
}
// fp16 MMA, fp32 accumulate; non-volatile so ptxas may schedule freely.
__device__ __forceinline__ void mma16816(float* c, const uint32_t* a,
                                         const uint32_t* b) {
    asm("mma.sync.aligned.m16n8k16.row.col.f32.f16.f16.f32 "
        "{%0,%1,%2,%3}, {%4,%5,%6,%7}, {%8,%9}, {%0,%1,%2,%3};"
        : "+f"(c[0]), "+f"(c[1]), "+f"(c[2]), "+f"(c[3])
        : "r"(a[0]), "r"(a[1]), "r"(a[2]), "r"(a[3]), "r"(b[0]), "r"(b[1]));
}
__device__ __forceinline__ float ex2(float x) {
    float r;
    asm("ex2.approx.ftz.f32 %0, %1;" : "=f"(r) : "f"(x));
    return r;
}
__device__ __forceinline__ uint32_t pack2h(float a, float b) {
    __half2 hv = __halves2half2(__float2half_rn(a), __float2half_rn(b));
    return *(uint32_t*)&hv;
}
#define CP_ASYNC(sa, ga) \
    asm volatile("cp.async.cg.shared.global [%0], [%1], 16;" :: "r"(sa), "l"(ga))
#define CP_COMMIT() asm volatile("cp.async.commit_group;" ::: "memory")
#define CP_WAIT0()  asm volatile("cp.async.wait_group 0;" ::: "memory")
#define CP_WAIT1()  asm volatile("cp.async.wait_group 1;" ::: "memory")

// ====================== setup kernels =======================================
__global__ void __launch_bounds__(64)
rope_init_kernel()
{
    int s = blockIdx.x, p = threadIdx.x;
    float inv = expf(-(float)p * 0.14391156831212787f); // ln(10000)/64
    float ang = (float)s * inv;
    float sn, cs;
    sincosf(ang, &sn, &cs);
    g_rope[s * 64 + p] = make_float2(cs, sn);
}

// fp32 -> fp16 (single)
__global__ void __launch_bounds__(256)
round_kernel(const float* __restrict__ src, __half* __restrict__ dst, int n)
{
    int i = (blockIdx.x * 256 + threadIdx.x) * 4;
    if (i >= n) return;
    float4 v = *(const float4*)(src + i);
    __half h[4] = {__float2half_rn(v.x), __float2half_rn(v.y),
                   __float2half_rn(v.z), __float2half_rn(v.w)};
    *(uint2*)(dst + i) = *(uint2*)h;
}

// four weight matrices -> fp16, z selects source
__global__ void __launch_bounds__(256)
round4_kernel(const float* __restrict__ s0, const float* __restrict__ s1,
              const float* __restrict__ s2, const float* __restrict__ s3,
              __half* __restrict__ dst, int n)
{
    const int z = blockIdx.y;
    const float* src = (z == 0) ? s0 : (z == 1) ? s1 : (z == 2) ? s2 : s3;
    int i = (blockIdx.x * 256 + threadIdx.x) * 4;
    if (i >= n) return;
    float4 v = *(const float4*)(src + i);
    __half h[4] = {__float2half_rn(v.x), __float2half_rn(v.y),
                   __float2half_rn(v.z), __float2half_rn(v.w)};
    *(uint2*)(dst + (size_t)z * n + i) = *(uint2*)h;
}

// ================== fp16 tensor-core GEMM (mma.sync path) ===================
// C[M,N] = A[M,K] @ W[N,K]^T + bias, K=2048, all-fp16, fp32 accum.
// Block tile 64(M) x 256(N), 8 warps 2x4, warp tile 32x64, BK=64 (4 k-steps),
// 2-stage cp.async pipeline, 2 CTAs/SM, 32 chunks (half the barriers of BK32).
// fused: z=0 Q (RoPE), z=1 K (RoPE), z=2 V. non-fused: fp32 [M,N] out.
#define BKG     64
#define LDSTR   144                      // 64 halfs = 128B + 16B pad
#define B_OFF   (64 * LDSTR)             // 9216
#define STG     (B_OFF + 256 * LDSTR)    // 46080
#define GSMEM   (2 * STG)                // 92160 per CTA (2 CTAs = 180KB)

__device__ __forceinline__ void g_load(uint32_t sbase,
    const __half* A0, const __half* B0, int k0, int tid)
{
#pragma unroll
    for (int rep = 0; rep < 2; rep++) {      // A: 64 rows x 8 chunks = 512
        int idx = tid + rep * 256;
        int row = idx >> 3, c8 = idx & 7;
        CP_ASYNC(sbase + row * LDSTR + c8 * 16,
                 A0 + (size_t)row * H_ + k0 + c8 * 8);
    }
#pragma unroll
    for (int rep = 0; rep < 8; rep++) {      // B: 256 rows x 8 chunks = 2048
        int idx = tid + rep * 256;
        int row = idx >> 3, c8 = idx & 7;
        CP_ASYNC(sbase + B_OFF + row * LDSTR + c8 * 16,
                 B0 + (size_t)row * H_ + k0 + c8 * 8);
    }
}

__global__ void __launch_bounds__(256, 2)
gemm_mma(const __half* __restrict__ Ain, const __half* __restrict__ WB,
         const float* __restrict__ b0, const float* __restrict__ b1,
         const float* __restrict__ b2,
         __half* o0, __half* o1, __half* o2,
         float* out, int fused)
{
    extern __shared__ char sm[];
    const uint32_t smb = smem_u32(sm);
    const int tid  = threadIdx.x;
    const int wid  = tid >> 5, lane = tid & 31;
    const int bm   = blockIdx.y * 64, bn = blockIdx.x * 256;
    const int wm   = (wid >> 2) * 32, wn = (wid & 3) * 64;

    const __half* W = WB;
    const float* bias = b0;
    __half* oh = nullptr;
    int mode = 2;                       // 2 = fp32 row-major out
    if (fused) {
        const int z = blockIdx.z;
        W += (size_t)z * H_ * H_;
        bias = (z == 0) ? b0 : (z == 1) ? b1 : b2;
        oh   = (z == 0) ? o0 : (z == 1) ? o1 : o2;
        mode = (z == 2) ? 0 : 1;        // 1 = RoPE+fp16, 0 = fp16
    }

    const __half* A0 = Ain + (size_t)bm * H_;
    const __half* B0 = W   + (size_t)bn * H_;

    float acc[2][8][4];
#pragma unroll
    for (int i = 0; i < 2; i++)
#pragma unroll
        for (int j = 0; j < 8; j++)
#pragma unroll
            for (int q = 0; q < 4; q++) acc[i][j][q] = 0.f;

    const int arow  = (lane & 7) + ((lane >> 3) & 1) * 8;
    const int acoff = ((lane >> 4) & 1) * 16;
    const int krow  = (lane & 7) + ((lane >> 4) & 1) * 8;
    const int kcoff = ((lane >> 3) & 1) * 16;

    g_load(smb, A0, B0, 0, tid);
    CP_COMMIT();

    const int NCH = H_ / BKG;   // 32
    for (int it = 0; it < NCH; it++) {
        if (it + 1 < NCH) {
            g_load(smb + ((it + 1) & 1) * STG, A0, B0, (it + 1) * BKG, tid);
            CP_COMMIT();
            CP_WAIT1();
        } else {
            CP_WAIT0();
        }
        __syncthreads();

        const uint32_t st = smb + (uint32_t)(it & 1) * STG;
#pragma unroll
        for (int ks = 0; ks < 4; ks++) {
            const int kb = ks * 32;
            uint32_t af[2][4];
#pragma unroll
            for (int mi = 0; mi < 2; mi++) {
                uint32_t off = (uint32_t)((wm + mi * 16 + arow) * LDSTR + kb + acoff);
                ldsm4(af[mi][0], af[mi][1], af[mi][2], af[mi][3], st + off);
            }
#pragma unroll
            for (int nq = 0; nq < 4; nq++) {
                uint32_t off = (uint32_t)((wn + nq * 16 + krow) * LDSTR + kb + kcoff);
                uint32_t b4[4];
                ldsm4(b4[0], b4[1], b4[2], b4[3], st + B_OFF + off);
                mma16816(acc[0][2*nq],   af[0], &b4[0]);
                mma16816(acc[1][2*nq],   af[1], &b4[0]);
                mma16816(acc[0][2*nq+1], af[0], &b4[2]);
                mma16816(acc[1][2*nq+1], af[1], &b4[2]);
            }
        }
        __syncthreads();
    }

    // ------------------------------ epilogue --------------------------------
    const int qrow = lane >> 2;
    const int qcol = (lane & 3) * 2;
#pragma unroll
    for (int mi = 0; mi < 2; mi++) {
#pragma unroll
        for (int half_ = 0; half_ < 2; half_++) {
            const int m  = bm + wm + mi * 16 + qrow + half_ * 8;
            const int sI = m & (S_ - 1);
#pragma unroll
            for (int nj = 0; nj < 8; nj++) {
                const int n0 = bn + wn + nj * 8 + qcol;
                float v0 = acc[mi][nj][half_ * 2 + 0] + bias[n0];
                float v1 = acc[mi][nj][half_ * 2 + 1] + bias[n0 + 1];
                if (mode == 1) {
                    int pr = (n0 & (D_ - 1)) >> 1;
                    float2 cssn = g_rope[sI * 64 + pr];
                    float e = v0, o = v1;
                    v0 = e * cssn.x - o * cssn.y;
                    v1 = o * cssn.x + e * cssn.y;
                }
                if (mode == 2) {
                    *(float2*)(out + (size_t)m * H_ + n0) = make_float2(v0, v1);
                } else {
                    int b = m >> 11;
                    int h = n0 >> 7;
                    int dd = n0 & (D_ - 1);
                    size_t idx = (((size_t)(b * NH_ + h) * S_ + sI) << 7) + dd;
                    *(uint32_t*)(oh + idx) = pack2h(v0, v1);
                }
            }
        }
    }
}

// ================= causal flash attention on tensor cores ===================
// 128 queries/block, 64-key tiles, 8 warps. Q fragments in registers.
// K, V single fp16 in smem; P single fp16 in registers.
// 3-stage cp.async pipeline, single barrier per tile.  (unchanged)
#define KSTR  272
#define ARRB  (64 * KSTR)             // 17408
#define STGB  (2 * ARRB)              // K, V per stage: 34816
#define ASMEM (3 * STGB)              // 104448

__device__ __forceinline__ void load_kv(uint32_t sb,
    const __half* kh, const __half* vh, size_t toff, int tid)
{
    const __half* srcs[2] = {kh + toff, vh + toff};
#pragma unroll
    for (int arr = 0; arr < 2; arr++)
#pragma unroll
        for (int rep = 0; rep < 4; rep++) {
            int ch = tid + rep * 256;
            int row = ch >> 4, c = ch & 15;
            CP_ASYNC(sb + arr * ARRB + row * KSTR + c * 16,
                     srcs[arr] + row * D_ + c * 8);
        }
}

__global__ void __launch_bounds__(256, 1)
attn_mma(const __half* __restrict__ Qg, const __half* __restrict__ Kg,
         const __half* __restrict__ Vg, __half* __restrict__ Og)
{
    extern __shared__ char sm[];
    const uint32_t smb = smem_u32(sm);
    const int tid = threadIdx.x, wid = tid >> 5, lane = tid & 31;
    const int qt = blockIdx.x, h = blockIdx.y, b = blockIdx.z;
    const int bh = b * NH_ + h;
    const size_t qoff = ((size_t)bh * S_ + qt * 128) * D_;
    const __half* kb = Kg + (size_t)bh * S_ * D_;
    const __half* vb = Vg + (size_t)bh * S_ * D_;

#pragma unroll
    for (int rep = 0; rep < 8; rep++) {
        int ch = tid + rep * 256;
        int row = ch >> 4, c = ch & 15;
        CP_ASYNC(smb + row * KSTR + c * 16, Qg + qoff + row * D_ + c * 8);
    }
    CP_COMMIT(); CP_WAIT0();
    __syncthreads();

    const int arow  = (lane & 7) + ((lane >> 3) & 1) * 8;
    const int acoff = ((lane >> 4) & 1) * 16;
    uint32_t qf[8][4];
#pragma unroll
    for (int kk = 0; kk < 8; kk++) {
        uint32_t off = (uint32_t)((wid * 16 + arow) * KSTR + kk * 32 + acoff);
        ldsm4(qf[kk][0], qf[kk][1], qf[kk][2], qf[kk][3], smb + off);
    }
    __syncthreads();   // Q staging area free for K/V

    const int NT = 2 * qt + 2;

    load_kv(smb,        kb, vb, 0,               tid); CP_COMMIT();
    load_kv(smb + STGB, kb, vb, (size_t)64 * D_, tid); CP_COMMIT();

    float o[16][4];
#pragma unroll
    for (int nt = 0; nt < 16; nt++)
#pragma unroll
        for (int c = 0; c < 4; c++) o[nt][c] = 0.f;
    float mrow[2] = {-1e30f, -1e30f}, lrow[2] = {0.f, 0.f};
    const float CSc = 0.12752551286084458f;   // log2(e)/sqrt(128)

    const int krow  = (lane & 7) + ((lane >> 4) & 1) * 8;
    const int kcoff = ((lane >> 3) & 1) * 16;

    for (int it = 0; it < NT; it++) {
        if (it == NT - 1) { CP_WAIT0(); } else { CP_WAIT1(); }
        __syncthreads();
        const uint32_t st = smb + (uint32_t)(it % 3) * STGB;

        float s[8][4];
#pragma unroll
        for (int nj = 0; nj < 8; nj++)
#pragma unroll
            for (int c = 0; c < 4; c++) s[nj][c] = 0.f;

#pragma unroll
        for (int kk = 0; kk < 8; kk++) {
#pragma unroll
            for (int g = 0; g < 4; g++) {
                uint32_t off = (uint32_t)((g * 16 + krow) * KSTR + kk * 32 + kcoff);
                uint32_t k4[4];
                ldsm4(k4[0], k4[1], k4[2], k4[3], st + off);
                mma16816(s[2*g],   qf[kk], &k4[0]);
                mma16816(s[2*g+1], qf[kk], &k4[2]);
            }
        }

        if (it >= 2 * qt) {
            const int q0r = qt * 128 + wid * 16 + (lane >> 2);
            const int kc  = it * 64 + (lane & 3) * 2;
#pragma unroll
            for (int nj = 0; nj < 8; nj++) {
                int kcol = kc + nj * 8;
                if (kcol     > q0r)     s[nj][0] = -1e30f;
                if (kcol + 1 > q0r)     s[nj][1] = -1e30f;
                if (kcol     > q0r + 8) s[nj][2] = -1e30f;
                if (kcol + 1 > q0r + 8) s[nj][3] = -1e30f;
            }
        }

        float tm0 = -1e30f, tm1 = -1e30f;
#pragma unroll
        for (int nj = 0; nj < 8; nj++) {
            tm0 = fmaxf(tm0, fmaxf(s[nj][0], s[nj][1]));
            tm1 = fmaxf(tm1, fmaxf(s[nj][2], s[nj][3]));
        }
        tm0 = fmaxf(tm0, __shfl_xor_sync(0xffffffffu, tm0, 1));
        tm0 = fmaxf(tm0, __shfl_xor_sync(0xffffffffu, tm0, 2));
        tm1 = fmaxf(tm1, __shfl_xor_sync(0xffffffffu, tm1, 1));
        tm1 = fmaxf(tm1, __shfl_xor_sync(0xffffffffu, tm1, 2));
        float mn0 = fmaxf(mrow[0], tm0), mn1 = fmaxf(mrow[1], tm1);
        float cor0 = ex2(CSc * (mrow[0] - mn0));
        float cor1 = ex2(CSc * (mrow[1] - mn1));
        mrow[0] = mn0; mrow[1] = mn1;
        float rs0 = 0.f, rs1 = 0.f;
#pragma unroll
        for (int nj = 0; nj < 8; nj++) {
            s[nj][0] = ex2(CSc * (s[nj][0] - mn0)); rs0 += s[nj][0];
            s[nj][1] = ex2(CSc * (s[nj][1] - mn0)); rs0 += s[nj][1];
            s[nj][2] = ex2(CSc * (s[nj][2] - mn1)); rs1 += s[nj][2];
            s[nj][3] = ex2(CSc * (s[nj][3] - mn1)); rs1 += s[nj][3];
        }
        rs0 += __shfl_xor_sync(0xffffffffu, rs0, 1);
        rs0 += __shfl_xor_sync(0xffffffffu, rs0, 2);
        rs1 += __shfl_xor_sync(0xffffffffu, rs1, 1);
        rs1 += __shfl_xor_sync(0xffffffffu, rs1, 2);
        lrow[0] = lrow[0] * cor0 + rs0;
        lrow[1] = lrow[1] * cor1 + rs1;
#pragma unroll
        for (int nt = 0; nt < 16; nt++) {
            o[nt][0] *= cor0; o[nt][1] *= cor0;
            o[nt][2] *= cor1; o[nt][3] *= cor1;
        }

        uint32_t pf[4][4];
#pragma unroll
        for (int t = 0; t < 4; t++) {
            pf[t][0] = pack2h(s[2*t][0],   s[2*t][1]);
            pf[t][1] = pack2h(s[2*t][2],   s[2*t][3]);
            pf[t][2] = pack2h(s[2*t+1][0], s[2*t+1][1]);
            pf[t][3] = pack2h(s[2*t+1][2], s[2*t+1][3]);
        }

#pragma unroll
        for (int t = 0; t < 4; t++) {
#pragma unroll
            for (int nc = 0; nc < 8; nc++) {
                uint32_t off = (uint32_t)((t * 16 + arow) * KSTR + nc * 32 + acoff);
                uint32_t v4[4];
                ldsm4t(v4[0], v4[1], v4[2], v4[3], st + ARRB + off);
                mma16816(o[2*nc],   pf[t], &v4[0]);
                mma16816(o[2*nc+1], pf[t], &v4[2]);
            }
        }

        if (it + 2 < NT) {
            load_kv(smb + (uint32_t)((it + 2) % 3) * STGB,
                    kb, vb, (size_t)(it + 2) * 64 * D_, tid);
            CP_COMMIT();
        }
    }

    const float inv0 = 1.f / lrow[0], inv1 = 1.f / lrow[1];
    const int q0 = qt * 128 + wid * 16 + (lane >> 2);
    const size_t base0 = ((size_t)(b * S_) + q0) * H_ + h * 128;
    const size_t base1 = base0 + (size_t)8 * H_;
#pragma unroll
    for (int nt = 0; nt < 16; nt++) {
        const int col = nt * 8 + (lane & 3) * 2;
        *(uint32_t*)(Og + base0 + col) = pack2h(o[nt][0] * inv0, o[nt][1] * inv0);
        *(uint32_t*)(Og + base1 + col) = pack2h(o[nt][2] * inv1, o[nt][3] * inv1);
    }
}

// ============================================================================
extern "C" void kernel_launch(void* const* d_in, const int* in_sizes, int n_in,
                              void* d_out, int out_size)
{
    const float* x  = (const float*)d_in[0];
    const float* Wq = (const float*)d_in[1];
    const float* bq = (const float*)d_in[2];
    const float* Wk = (const float*)d_in[3];
    const float* bk = (const float*)d_in[4];
    const float* Wv = (const float*)d_in[5];
    const float* bv = (const float*)d_in[6];
    const float* Wo = (const float*)d_in[7];
    const float* bo = (const float*)d_in[8];
    float* out = (float*)d_out;

    __half *xp, *wp, *ap, *qp, *kp, *vp;
    cudaGetSymbolAddress((void**)&xp, g_x);
    cudaGetSymbolAddress((void**)&wp, g_w);
    cudaGetSymbolAddress((void**)&ap, g_a);
    cudaGetSymbolAddress((void**)&qp, g_q);
    cudaGetSymbolAddress((void**)&kp, g_k);
    cudaGetSymbolAddress((void**)&vp, g_v);

    cudaFuncSetAttribute(gemm_mma,
                         cudaFuncAttributeMaxDynamicSharedMemorySize, GSMEM);
    cudaFuncSetAttribute(attn_mma,
                         cudaFuncAttributeMaxDynamicSharedMemorySize, ASMEM);

    const int nX = M_ * H_;
    const int nW = H_ * H_;
    rope_init_kernel<<<S_, 64>>>();
    round_kernel<<<nX / 1024, 256>>>(x, xp, nX);
    round4_kernel<<<dim3(nW / 1024, 4), 256>>>(Wq, Wk, Wv, Wo, wp, nW);

    dim3 gq(H_ / 256, M_ / 64, 3);
    gemm_mma<<<gq, 256, GSMEM>>>(xp, wp, bq, bk, bv,
                                 qp, kp, vp, nullptr, 1);

    attn_mma<<<dim3(S_ / 128, NH_, B_), 256, ASMEM>>>(qp, kp, vp, ap);

    dim3 go(H_ / 256, M_ / 64, 1);
    gemm_mma<<<go, 256, GSMEM>>>(ap, wp + 3*(size_t)nW,
                                 bo, nullptr, nullptr,
                                 nullptr, nullptr, nullptr,
                                 out, 0);
}

// round 14
// speedup vs baseline: 2.5897x; 1.0107x over previous
#include <cuda_runtime.h>
#include <cuda_fp16.h>
#include <math.h>
#include <stdint.h>

#define B_   2
#define S_   2048
#define H_   2048
#define NH_  16
#define D_   128
#define M_   (B_*S_)          // 4096 rows for all GEMMs

// ---------------- scratch (static device globals; no allocation) ------------
__device__ __align__(256) __half g_x[(size_t)M_*H_];         // x, fp16
__device__ __align__(256) __half g_w[(size_t)4*H_*H_];       // Wq,Wk,Wv,Wo fp16
__device__ __align__(256) __half g_a[(size_t)M_*H_];         // attn out fp16
__device__ __align__(256) __half g_q[(size_t)B_*NH_*S_*D_];
__device__ __align__(256) __half g_k[(size_t)B_*NH_*S_*D_];
__device__ __align__(256) __half g_v[(size_t)B_*NH_*S_*D_];
__device__ __align__(256) float2 g_rope[(size_t)S_ * 64];    // (cos, sin)

// =========================== helpers ========================================
__device__ __forceinline__ uint32_t smem_u32(const void* p) {
    uint32_t a;
    asm("{ .reg .u64 t; cvta.to.shared.u64 t, %1; cvt.u32.u64 %0, t; }"
        : "=r"(a) : "l"(p));
    return a;
}
__device__ __forceinline__ void ldsm4(uint32_t& r0, uint32_t& r1,
                                      uint32_t& r2, uint32_t& r3, uint32_t a) {
    asm volatile("ldmatrix.sync.aligned.m8n8.x4.shared.b16 {%0,%1,%2,%3}, [%4];"
                 : "=r"(r0), "=r"(r1), "=r"(r2), "=r"(r3) : "r"(a));
}
__device__ __forceinline__ void ldsm4t(uint32_t& r0, uint32_t& r1,
                                       uint32_t& r2, uint32_t& r3, uint32_t a) {
    asm volatile("ldmatrix.sync.aligned.m8n8.x4.trans.shared.b16 {%0,%1,%2,%3}, [%4];"
                 : "=r"(r0), "=r"(r1), "=r"(r2), "=r"(r3) : "r"(a));
}
// fp16 MMA, fp32 accumulate; non-volatile so ptxas may schedule freely.
__device__ __forceinline__ void mma16816(float* c, const uint32_t* a,
                                         const uint32_t* b) {
    asm("mma.sync.aligned.m16n8k16.row.col.f32.f16.f16.f32 "
        "{%0,%1,%2,%3}, {%4,%5,%6,%7}, {%8,%9}, {%0,%1,%2,%3};"
        : "+f"(c[0]), "+f"(c[1]), "+f"(c[2]), "+f"(c[3])
        : "r"(a[0]), "r"(a[1]), "r"(a[2]), "r"(a[3]), "r"(b[0]), "r"(b[1]));
}
__device__ __forceinline__ float ex2(float x) {
    float r;
    asm("ex2.approx.ftz.f32 %0, %1;" : "=f"(r) : "f"(x));
    return r;
}
__device__ __forceinline__ uint32_t pack2h(float a, float b) {
    __half2 hv = __halves2half2(__float2half_rn(a), __float2half_rn(b));
    return *(uint32_t*)&hv;
}
#define CP_ASYNC(sa, ga) \
    asm volatile("cp.async.cg.shared.global [%0], [%1], 16;" :: "r"(sa), "l"(ga))
#define CP_COMMIT() asm volatile("cp.async.commit_group;" ::: "memory")
#define CP_WAIT0()  asm volatile("cp.async.wait_group 0;" ::: "memory")
#define CP_WAIT1()  asm volatile("cp.async.wait_group 1;" ::: "memory")

// ====================== setup kernels =======================================
__global__ void __launch_bounds__(64)
rope_init_kernel()
{
    int s = blockIdx.x, p = threadIdx.x;
    float inv = expf(-(float)p * 0.14391156831212787f); // ln(10000)/64
    float ang = (float)s * inv;
    float sn, cs;
    sincosf(ang, &sn, &cs);
    g_rope[s * 64 + p] = make_float2(cs, sn);
}

// fp32 -> fp16 (single)
__global__ void __launch_bounds__(256)
round_kernel(const float* __restrict__ src, __half* __restrict__ dst, int n)
{
    int i = (blockIdx.x * 256 + threadIdx.x) * 4;
    if (i >= n) return;
    float4 v = *(const float4*)(src + i);
    __half h[4] = {__float2half_rn(v.x), __float2half_rn(v.y),
                   __float2half_rn(v.z), __float2half_rn(v.w)};
    *(uint2*)(dst + i) = *(uint2*)h;
}

// four weight matrices -> fp16, z selects source
__global__ void __launch_bounds__(256)
round4_kernel(const float* __restrict__ s0, const float* __restrict__ s1,
              const float* __restrict__ s2, const float* __restrict__ s3,
              __half* __restrict__ dst, int n)
{
    const int z = blockIdx.y;
    const float* src = (z == 0) ? s0 : (z == 1) ? s1 : (z == 2) ? s2 : s3;
    int i = (blockIdx.x * 256 + threadIdx.x) * 4;
    if (i >= n) return;
    float4 v = *(const float4*)(src + i);
    __half h[4] = {__float2half_rn(v.x), __float2half_rn(v.y),
                   __float2half_rn(v.z), __float2half_rn(v.w)};
    *(uint2*)(dst + (size_t)z * n + i) = *(uint2*)h;
}

// ================== fp16 tensor-core GEMM (mma.sync path) ===================
// (unchanged from R12: BK=64, 64x256 block, 2 CTAs/SM, 2-stage — prefetch is
//  issued BEFORE wait+barrier, so 2 stages are race-free here)
#define BKG     64
#define LDSTR   144
#define B_OFF   (64 * LDSTR)             // 9216
#define STG     (B_OFF + 256 * LDSTR)    // 46080
#define GSMEM   (2 * STG)                // 92160 per CTA

__device__ __forceinline__ void g_load(uint32_t sbase,
    const __half* A0, const __half* B0, int k0, int tid)
{
#pragma unroll
    for (int rep = 0; rep < 2; rep++) {      // A: 64 rows x 8 chunks = 512
        int idx = tid + rep * 256;
        int row = idx >> 3, c8 = idx & 7;
        CP_ASYNC(sbase + row * LDSTR + c8 * 16,
                 A0 + (size_t)row * H_ + k0 + c8 * 8);
    }
#pragma unroll
    for (int rep = 0; rep < 8; rep++) {      // B: 256 rows x 8 chunks = 2048
        int idx = tid + rep * 256;
        int row = idx >> 3, c8 = idx & 7;
        CP_ASYNC(sbase + B_OFF + row * LDSTR + c8 * 16,
                 B0 + (size_t)row * H_ + k0 + c8 * 8);
    }
}

__global__ void __launch_bounds__(256, 2)
gemm_mma(const __half* __restrict__ Ain, const __half* __restrict__ WB,
         const float* __restrict__ b0, const float* __restrict__ b1,
         const float* __restrict__ b2,
         __half* o0, __half* o1, __half* o2,
         float* out, int fused)
{
    extern __shared__ char sm[];
    const uint32_t smb = smem_u32(sm);
    const int tid  = threadIdx.x;
    const int wid  = tid >> 5, lane = tid & 31;
    const int bm   = blockIdx.y * 64, bn = blockIdx.x * 256;
    const int wm   = (wid >> 2) * 32, wn = (wid & 3) * 64;

    const __half* W = WB;
    const float* bias = b0;
    __half* oh = nullptr;
    int mode = 2;
    if (fused) {
        const int z = blockIdx.z;
        W += (size_t)z * H_ * H_;
        bias = (z == 0) ? b0 : (z == 1) ? b1 : b2;
        oh   = (z == 0) ? o0 : (z == 1) ? o1 : o2;
        mode = (z == 2) ? 0 : 1;
    }

    const __half* A0 = Ain + (size_t)bm * H_;
    const __half* B0 = W   + (size_t)bn * H_;

    float acc[2][8][4];
#pragma unroll
    for (int i = 0; i < 2; i++)
#pragma unroll
        for (int j = 0; j < 8; j++)
#pragma unroll
            for (int q = 0; q < 4; q++) acc[i][j][q] = 0.f;

    const int arow  = (lane & 7) + ((lane >> 3) & 1) * 8;
    const int acoff = ((lane >> 4) & 1) * 16;
    const int krow  = (lane & 7) + ((lane >> 4) & 1) * 8;
    const int kcoff = ((lane >> 3) & 1) * 16;

    g_load(smb, A0, B0, 0, tid);
    CP_COMMIT();

    const int NCH = H_ / BKG;   // 32
    for (int it = 0; it < NCH; it++) {
        if (it + 1 < NCH) {
            g_load(smb + ((it + 1) & 1) * STG, A0, B0, (it + 1) * BKG, tid);
            CP_COMMIT();
            CP_WAIT1();
        } else {
            CP_WAIT0();
        }
        __syncthreads();

        const uint32_t st = smb + (uint32_t)(it & 1) * STG;
#pragma unroll
        for (int ks = 0; ks < 4; ks++) {
            const int kb = ks * 32;
            uint32_t af[2][4];
#pragma unroll
            for (int mi = 0; mi < 2; mi++) {
                uint32_t off = (uint32_t)((wm + mi * 16 + arow) * LDSTR + kb + acoff);
                ldsm4(af[mi][0], af[mi][1], af[mi][2], af[mi][3], st + off);
            }
#pragma unroll
            for (int nq = 0; nq < 4; nq++) {
                uint32_t off = (uint32_t)((wn + nq * 16 + krow) * LDSTR + kb + kcoff);
                uint32_t b4[4];
                ldsm4(b4[0], b4[1], b4[2], b4[3], st + B_OFF + off);
                mma16816(acc[0][2*nq],   af[0], &b4[0]);
                mma16816(acc[1][2*nq],   af[1], &b4[0]);
                mma16816(acc[0][2*nq+1], af[0], &b4[2]);
                mma16816(acc[1][2*nq+1], af[1], &b4[2]);
            }
        }
        __syncthreads();
    }

    // ------------------------------ epilogue --------------------------------
    const int qrow = lane >> 2;
    const int qcol = (lane & 3) * 2;
#pragma unroll
    for (int mi = 0; mi < 2; mi++) {
#pragma unroll
        for (int half_ = 0; half_ < 2; half_++) {
            const int m  = bm + wm + mi * 16 + qrow + half_ * 8;
            const int sI = m & (S_ - 1);
#pragma unroll
            for (int nj = 0; nj < 8; nj++) {
                const int n0 = bn + wn + nj * 8 + qcol;
                float v0 = acc[mi][nj][half_ * 2 + 0] + bias[n0];
                float v1 = acc[mi][nj][half_ * 2 + 1] + bias[n0 + 1];
                if (mode == 1) {
                    int pr = (n0 & (D_ - 1)) >> 1;
                    float2 cssn = g_rope[sI * 64 + pr];
                    float e = v0, o = v1;
                    v0 = e * cssn.x - o * cssn.y;
                    v1 = o * cssn.x + e * cssn.y;
                }
                if (mode == 2) {
                    *(float2*)(out + (size_t)m * H_ + n0) = make_float2(v0, v1);
                } else {
                    int b = m >> 11;
                    int h = n0 >> 7;
                    int dd = n0 & (D_ - 1);
                    size_t idx = (((size_t)(b * NH_ + h) * S_ + sI) << 7) + dd;
                    *(uint32_t*)(oh + idx) = pack2h(v0, v1);
                }
            }
        }
    }
}

// ================= causal flash attention on tensor cores ===================
// 128 queries/block, 128-key tiles, 8 warps, Q fragments in registers,
// K/V single fp16 in smem, **3-stage** cp.async pipeline (prefetch it+2 into
// (it+2)%3 = slot last read at it-1, protected by this iteration's barrier).
// Longest blocks launch first (reversed qt).
#define KSTR  272
#define ARRB  (128 * KSTR)            // 34816 (K or V, 128 rows)
#define STGB  (2 * ARRB)              // K+V per stage: 69632
#define ASMEM (3 * STGB)              // 208896

__device__ __forceinline__ void load_kv(uint32_t sb,
    const __half* kh, const __half* vh, size_t toff, int tid)
{
    const __half* srcs[2] = {kh + toff, vh + toff};
#pragma unroll
    for (int arr = 0; arr < 2; arr++)
#pragma unroll
        for (int rep = 0; rep < 8; rep++) {       // 128 rows x 16 chunks
            int ch = tid + rep * 256;
            int row = ch >> 4, c = ch & 15;
            CP_ASYNC(sb + arr * ARRB + row * KSTR + c * 16,
                     srcs[arr] + row * D_ + c * 8);
        }
}

__global__ void __launch_bounds__(256, 1)
attn_mma(const __half* __restrict__ Qg, const __half* __restrict__ Kg,
         const __half* __restrict__ Vg, __half* __restrict__ Og)
{
    extern __shared__ char sm[];
    const uint32_t smb = smem_u32(sm);
    const int tid = threadIdx.x, wid = tid >> 5, lane = tid & 31;
    const int qt = (int)(gridDim.x - 1 - blockIdx.x);   // longest first
    const int h = blockIdx.y, b = blockIdx.z;
    const int bh = b * NH_ + h;
    const size_t qoff = ((size_t)bh * S_ + qt * 128) * D_;
    const __half* kb = Kg + (size_t)bh * S_ * D_;
    const __half* vb = Vg + (size_t)bh * S_ * D_;

    // ---- stage Q into slot0; extract fragments to registers ----------------
#pragma unroll
    for (int rep = 0; rep < 8; rep++) {
        int ch = tid + rep * 256;
        int row = ch >> 4, c = ch & 15;
        CP_ASYNC(smb + row * KSTR + c * 16, Qg + qoff + row * D_ + c * 8);
    }
    CP_COMMIT(); CP_WAIT0();
    __syncthreads();

    const int arow  = (lane & 7) + ((lane >> 3) & 1) * 8;
    const int acoff = ((lane >> 4) & 1) * 16;
    uint32_t qf[8][4];
#pragma unroll
    for (int kk = 0; kk < 8; kk++) {
        uint32_t off = (uint32_t)((wid * 16 + arow) * KSTR + kk * 32 + acoff);
        ldsm4(qf[kk][0], qf[kk][1], qf[kk][2], qf[kk][3], smb + off);
    }
    __syncthreads();   // Q staging area free for K/V

    const int NT = qt + 1;                      // 128-key tiles

    load_kv(smb,        kb, vb, 0, tid); CP_COMMIT();
    if (NT > 1) { load_kv(smb + STGB, kb, vb, (size_t)128 * D_, tid); }
    CP_COMMIT();   // commit (possibly empty) group so wait-counts line up

    float o[16][4];
#pragma unroll
    for (int nt = 0; nt < 16; nt++)
#pragma unroll
        for (int c = 0; c < 4; c++) o[nt][c] = 0.f;
    float mrow[2] = {-1e30f, -1e30f}, lrow[2] = {0.f, 0.f};
    const float CSc = 0.12752551286084458f;   // log2(e)/sqrt(128)

    const int krow  = (lane & 7) + ((lane >> 4) & 1) * 8;
    const int kcoff = ((lane >> 3) & 1) * 16;

    for (int it = 0; it < NT; it++) {
        if (it == NT - 1) { CP_WAIT0(); } else { CP_WAIT1(); }
        __syncthreads();
        const uint32_t st = smb + (uint32_t)(it % 3) * STGB;

        // ---------------- S = Q @ K^T (128 keys) ----------------------------
        float s[16][4];
#pragma unroll
        for (int nj = 0; nj < 16; nj++)
#pragma unroll
            for (int c = 0; c < 4; c++) s[nj][c] = 0.f;

#pragma unroll
        for (int kk = 0; kk < 8; kk++) {
#pragma unroll
            for (int g = 0; g < 8; g++) {
                uint32_t off = (uint32_t)((g * 16 + krow) * KSTR + kk * 32 + kcoff);
                uint32_t k4[4];
                ldsm4(k4[0], k4[1], k4[2], k4[3], st + off);
                mma16816(s[2*g],   qf[kk], &k4[0]);
                mma16816(s[2*g+1], qf[kk], &k4[2]);
            }
        }

        // ---------------- causal mask (diagonal tile only) ------------------
        if (it == qt) {
            const int q0r = qt * 128 + wid * 16 + (lane >> 2);
            const int kc  = it * 128 + (lane & 3) * 2;
#pragma unroll
            for (int nj = 0; nj < 16; nj++) {
                int kcol = kc + nj * 8;
                if (kcol     > q0r)     s[nj][0] = -1e30f;
                if (kcol + 1 > q0r)     s[nj][1] = -1e30f;
                if (kcol     > q0r + 8) s[nj][2] = -1e30f;
                if (kcol + 1 > q0r + 8) s[nj][3] = -1e30f;
            }
        }

        // ---------------- online softmax (one pass per 128 keys) ------------
        float tm0 = -1e30f, tm1 = -1e30f;
#pragma unroll
        for (int nj = 0; nj < 16; nj++) {
            tm0 = fmaxf(tm0, fmaxf(s[nj][0], s[nj][1]));
            tm1 = fmaxf(tm1, fmaxf(s[nj][2], s[nj][3]));
        }
        tm0 = fmaxf(tm0, __shfl_xor_sync(0xffffffffu, tm0, 1));
        tm0 = fmaxf(tm0, __shfl_xor_sync(0xffffffffu, tm0, 2));
        tm1 = fmaxf(tm1, __shfl_xor_sync(0xffffffffu, tm1, 1));
        tm1 = fmaxf(tm1, __shfl_xor_sync(0xffffffffu, tm1, 2));
        float mn0 = fmaxf(mrow[0], tm0), mn1 = fmaxf(mrow[1], tm1);
        float cor0 = ex2(CSc * (mrow[0] - mn0));
        float cor1 = ex2(CSc * (mrow[1] - mn1));
        mrow[0] = mn0; mrow[1] = mn1;
        float rs0 = 0.f, rs1 = 0.f;
#pragma unroll
        for (int nj = 0; nj < 16; nj++) {
            s[nj][0] = ex2(CSc * (s[nj][0] - mn0)); rs0 += s[nj][0];
            s[nj][1] = ex2(CSc * (s[nj][1] - mn0)); rs0 += s[nj][1];
            s[nj][2] = ex2(CSc * (s[nj][2] - mn1)); rs1 += s[nj][2];
            s[nj][3] = ex2(CSc * (s[nj][3] - mn1)); rs1 += s[nj][3];
        }
        rs0 += __shfl_xor_sync(0xffffffffu, rs0, 1);
        rs0 += __shfl_xor_sync(0xffffffffu, rs0, 2);
        rs1 += __shfl_xor_sync(0xffffffffu, rs1, 1);
        rs1 += __shfl_xor_sync(0xffffffffu, rs1, 2);
        lrow[0] = lrow[0] * cor0 + rs0;
        lrow[1] = lrow[1] * cor1 + rs1;
#pragma unroll
        for (int nt = 0; nt < 16; nt++) {
            o[nt][0] *= cor0; o[nt][1] *= cor0;
            o[nt][2] *= cor1; o[nt][3] *= cor1;
        }

        // ---------------- P -> fp16 a-frags (registers only) ----------------
        uint32_t pf[8][4];
#pragma unroll
        for (int t = 0; t < 8; t++) {
            pf[t][0] = pack2h(s[2*t][0],   s[2*t][1]);
            pf[t][1] = pack2h(s[2*t][2],   s[2*t][3]);
            pf[t][2] = pack2h(s[2*t+1][0], s[2*t+1][1]);
            pf[t][3] = pack2h(s[2*t+1][2], s[2*t+1][3]);
        }

        // ---------------- O += P @ V (128 keys) -----------------------------
#pragma unroll
        for (int t = 0; t < 8; t++) {
#pragma unroll
            for (int nc = 0; nc < 8; nc++) {
                uint32_t off = (uint32_t)((t * 16 + arow) * KSTR + nc * 32 + acoff);
                uint32_t v4[4];
                ldsm4t(v4[0], v4[1], v4[2], v4[3], st + ARRB + off);
                mma16816(o[2*nc],   pf[t], &v4[0]);
                mma16816(o[2*nc+1], pf[t], &v4[2]);
            }
        }

        if (it + 2 < NT) {
            load_kv(smb + (uint32_t)((it + 2) % 3) * STGB,
                    kb, vb, (size_t)(it + 2) * 128 * D_, tid);
            CP_COMMIT();
        }
    }

    // ---------------- epilogue: O/l -> fp16, [b*s, h*d] ---------------------
    const float inv0 = 1.f / lrow[0], inv1 = 1.f / lrow[1];
    const int q0 = qt * 128 + wid * 16 + (lane >> 2);
    const size_t base0 = ((size_t)(b * S_) + q0) * H_ + h * 128;
    const size_t base1 = base0 + (size_t)8 * H_;
#pragma unroll
    for (int nt = 0; nt < 16; nt++) {
        const int col = nt * 8 + (lane & 3) * 2;
        *(uint32_t*)(Og + base0 + col) = pack2h(o[nt][0] * inv0, o[nt][1] * inv0);
        *(uint32_t*)(Og + base1 + col) = pack2h(o[nt][2] * inv1, o[nt][3] * inv1);
    }
}

// ============================================================================
extern "C" void kernel_launch(void* const* d_in, const int* in_sizes, int n_in,
                              void* d_out, int out_size)
{
    const float* x  = (const float*)d_in[0];
    const float* Wq = (const float*)d_in[1];
    const float* bq = (const float*)d_in[2];
    const float* Wk = (const float*)d_in[3];
    const float* bk = (const float*)d_in[4];
    const float* Wv = (const float*)d_in[5];
    const float* bv = (const float*)d_in[6];
    const float* Wo = (const float*)d_in[7];
    const float* bo = (const float*)d_in[8];
    float* out = (float*)d_out;

    __half *xp, *wp, *ap, *qp, *kp, *vp;
    cudaGetSymbolAddress((void**)&xp, g_x);
    cudaGetSymbolAddress((void**)&wp, g_w);
    cudaGetSymbolAddress((void**)&ap, g_a);
    cudaGetSymbolAddress((void**)&qp, g_q);
    cudaGetSymbolAddress((void**)&kp, g_k);
    cudaGetSymbolAddress((void**)&vp, g_v);

    cudaFuncSetAttribute(gemm_mma,
                         cudaFuncAttributeMaxDynamicSharedMemorySize, GSMEM);
    cudaFuncSetAttribute(attn_mma,
                         cudaFuncAttributeMaxDynamicSharedMemorySize, ASMEM);

    const int nX = M_ * H_;
    const int nW = H_ * H_;
    rope_init_kernel<<<S_, 64>>>();
    round_kernel<<<nX / 1024, 256>>>(x, xp, nX);
    round4_kernel<<<dim3(nW / 1024, 4), 256>>>(Wq, Wk, Wv, Wo, wp, nW);

    dim3 gq(H_ / 256, M_ / 64, 3);
    gemm_mma<<<gq, 256, GSMEM>>>(xp, wp, bq, bk, bv,
                                 qp, kp, vp, nullptr, 1);

    attn_mma<<<dim3(S_ / 128, NH_, B_), 256, ASMEM>>>(qp, kp, vp, ap);

    dim3 go(H_ / 256, M_ / 64, 1);
    gemm_mma<<<go, 256, GSMEM>>>(ap, wp + 3*(size_t)nW,
                                 bo, nullptr, nullptr,
                                 nullptr, nullptr, nullptr,
                                 out, 0);
}